// round 4
// baseline (speedup 1.0000x reference)
#include <cuda_runtime.h>
#include <math.h>

#define N_NODES 10000
#define N_EDGES 160000
#define WN 640
#define C110 0.57735026918962576451f   /* 1/sqrt(3) */
#define C111 0.70710678118654752440f   /* 1/sqrt(2) */

#define CHUNK 256                      /* edges per chunk: 128 threads x 2 edges */
#define NCHUNK (N_EDGES / CHUNK)       /* 625, exact */
#define EGRID 296                      /* persistent CTAs (2 per SM) */

typedef unsigned long long u64;

// ---------------- device scratch (no runtime allocation allowed) ----------------
__device__ float g_W2kT[WN * 32];
__device__ float g_W2vT[WN * 32];
__device__ float g_q[N_NODES * 40];
__device__ float g_attn[N_EDGES];
__device__ float g_vT[40 * (size_t)N_EDGES];
__device__ int   g_m[N_NODES];
__device__ float g_denom[N_NODES];
__device__ float g_numer[40 * N_NODES];
__device__ float g_pre[40 * N_NODES];
__device__ float g_stats[80];
__device__ int   g_ticket;

// ---------------- packed f32x2 helpers ----------------
__device__ __forceinline__ u64 fma2(u64 a, u64 b, u64 c) {
    u64 d;
    asm("fma.rn.f32x2 %0, %1, %2, %3;" : "=l"(d) : "l"(a), "l"(b), "l"(c));
    return d;
}
__device__ __forceinline__ u64 pack2(float lo, float hi) {
    u64 r;
    asm("mov.b64 %0, {%1, %2};" : "=l"(r) : "f"(lo), "f"(hi));
    return r;
}
__device__ __forceinline__ float sum2(u64 v) {
    float a, b;
    asm("mov.b64 {%0, %1}, %2;" : "=f"(a), "=f"(b) : "l"(v));
    return a + b;
}

// monotone float<->int key for atomicMax
__device__ __forceinline__ int fkey(float f) {
    int b = __float_as_int(f);
    return (b >= 0) ? b : (int)(b ^ 0x7FFFFFFF);
}
__device__ __forceinline__ float fdec(int k) {
    return (k >= 0) ? __int_as_float(k) : __int_as_float((int)(k ^ 0x7FFFFFFF));
}

// ---------------- prep kernels ----------------
__global__ void k_init() {
    int i = blockIdx.x * 256 + threadIdx.x;
    if (i < 40 * N_NODES) g_numer[i] = 0.0f;
    if (i < N_NODES) { g_denom[i] = 0.0f; g_m[i] = (int)0x807FFFFFu; /* key(-inf) */ }
    if (i < 80) g_stats[i] = 0.0f;
    if (i == 0) g_ticket = 0;
}

__global__ void k_transpose(const float* __restrict__ kw2, const float* __restrict__ vw2) {
    int i = blockIdx.x * 256 + threadIdx.x;
    if (i < WN * 32) {
        int j = i / WN, c = i % WN;
        g_W2kT[c * 32 + j] = kw2[i];
        g_W2vT[c * 32 + j] = vw2[i];
    }
}

__global__ void k_q(const float* __restrict__ atom, const float* __restrict__ Wqs,
                    const float* __restrict__ Wqv) {
    int t = blockIdx.x * 256 + threadIdx.x;
    if (t >= 40 * N_NODES) return;
    int n = t / 40, f = t % 40;
    const float* a = atom + (size_t)n * 40;
    float acc = 0.0f;
    if (f < 16) {
#pragma unroll
        for (int i = 0; i < 16; i++) acc = fmaf(a[i], Wqs[i * 16 + f], acc);
    } else {
        int o = (f - 16) / 3, d = (f - 16) % 3;
#pragma unroll
        for (int i = 0; i < 8; i++) acc = fmaf(a[16 + i * 3 + d], Wqv[i * 8 + o], acc);
    }
    g_q[t] = acc;
}

// ---------------- shared 2-edge dot over one 32-wide column ----------------
__device__ __forceinline__ void dot2e(const float* __restrict__ w,
                                      const u64 (&ha)[16], const u64 (&hb)[16],
                                      float& r0, float& r1) {
    const ulonglong2* wp = (const ulonglong2*)w;
    u64 a0 = 0, b0 = 0, a1 = 0, b1 = 0;
#pragma unroll
    for (int j = 0; j < 4; j++) {
        ulonglong2 w1 = wp[2 * j], w2 = wp[2 * j + 1];
        a0 = fma2(ha[4 * j + 0], w1.x, a0);
        b0 = fma2(ha[4 * j + 1], w1.y, b0);
        a0 = fma2(ha[4 * j + 2], w2.x, a0);
        b0 = fma2(ha[4 * j + 3], w2.y, b0);
        a1 = fma2(hb[4 * j + 0], w1.x, a1);
        b1 = fma2(hb[4 * j + 1], w1.y, b1);
        a1 = fma2(hb[4 * j + 2], w2.x, a1);
        b1 = fma2(hb[4 * j + 3], w2.y, b1);
    }
    r0 = sum2(a0) + sum2(b0);
    r1 = sum2(a1) + sum2(b1);
}

// ---------------- MLP layer-1 for two edges (shared weight loads) ----------------
__device__ __forceinline__ void load_ef2(const float* __restrict__ ef_g, int e, u64 (&ef2)[16]) {
    const float4* p = (const float4*)(ef_g + (size_t)e * 32);
#pragma unroll
    for (int i = 0; i < 8; i++) {
        float4 v = __ldg(p + i);
        ef2[2 * i + 0] = pack2(v.x, v.y);
        ef2[2 * i + 1] = pack2(v.z, v.w);
    }
}

__device__ __forceinline__ void mlp1_2(const float* __restrict__ sW1T,
                                       const float* __restrict__ sB1,
                                       const float* __restrict__ ef_g, int e0, int e1,
                                       u64 (&h2a)[16], u64 (&h2b)[16]) {
    u64 efa[16], efb[16];
    load_ef2(ef_g, e0, efa);
    load_ef2(ef_g, e1, efb);
#pragma unroll 1
    for (int c = 0; c < 16; c++) {
        float r0a, r0b, r1a, r1b;
        dot2e(sW1T + (2 * c) * 32, efa, efb, r0a, r0b);
        dot2e(sW1T + (2 * c + 1) * 32, efa, efb, r1a, r1b);
        float b0 = sB1[2 * c], b1 = sB1[2 * c + 1];
        h2a[c] = pack2(fmaxf(r0a + b0, 0.0f), fmaxf(r1a + b1, 0.0f));
        h2b[c] = pack2(fmaxf(r0b + b0, 0.0f), fmaxf(r1b + b1, 0.0f));
    }
}

// ---------------- coefficient slab writers ----------------
// slabA per edge (24 floats): [0..15]=x_s, [16..23]=C110*dot(x_v, sh_v)
__device__ __forceinline__ void write_slabA(const float* __restrict__ atom, int node,
                                            float* __restrict__ sl,
                                            float s0, float s1, float s2) {
    const float4* p = (const float4*)(atom + (size_t)node * 40);
#pragma unroll
    for (int i = 0; i < 4; i++) {
        float4 v = __ldg(p + i);
        sl[4 * i + 0] = v.x; sl[4 * i + 1] = v.y; sl[4 * i + 2] = v.z; sl[4 * i + 3] = v.w;
    }
    float xv[24];
#pragma unroll
    for (int i = 0; i < 6; i++) {
        float4 v = __ldg(p + 4 + i);
        xv[4 * i + 0] = v.x; xv[4 * i + 1] = v.y; xv[4 * i + 2] = v.z; xv[4 * i + 3] = v.w;
    }
#pragma unroll
    for (int i = 0; i < 8; i++)
        sl[16 + i] = C110 * (xv[3 * i] * s0 + xv[3 * i + 1] * s1 + xv[3 * i + 2] * s2);
}

// slabB per edge (48 floats): [0..23]=x_v, [24..47]=C111*cross(x_v, sh_v)
__device__ __forceinline__ void write_slabB(const float* __restrict__ atom, int node,
                                            float* __restrict__ sl,
                                            float s0, float s1, float s2) {
    const float4* p = (const float4*)(atom + (size_t)node * 40);
    float xv[24];
#pragma unroll
    for (int i = 0; i < 6; i++) {
        float4 v = __ldg(p + 4 + i);
        xv[4 * i + 0] = v.x; xv[4 * i + 1] = v.y; xv[4 * i + 2] = v.z; xv[4 * i + 3] = v.w;
    }
#pragma unroll
    for (int i = 0; i < 8; i++) {
        float a0 = xv[3 * i], a1 = xv[3 * i + 1], a2 = xv[3 * i + 2];
        sl[i * 3 + 0] = a0; sl[i * 3 + 1] = a1; sl[i * 3 + 2] = a2;
        sl[24 + i * 3 + 0] = C111 * (a1 * s2 - a2 * s1);
        sl[24 + i * 3 + 1] = C111 * (a2 * s0 - a0 * s2);
        sl[24 + i * 3 + 2] = C111 * (a0 * s1 - a1 * s0);
    }
}

// ---------------- GEMM+fold phases (2 edges, immediate fold) ----------------
// Phase A: blocks 1 (cols 0..255) and 2 (cols 256..383); tile base = col 0.
__device__ __forceinline__ void phaseA(const float* __restrict__ sW2, const float* __restrict__ sB2,
                                       const u64 (&h0)[16], const u64 (&h1)[16],
                                       const float* __restrict__ sl0, const float* __restrict__ sl1,
                                       float shs0, float shs1,
                                       float (&os0)[16], float (&os1)[16]) {
#pragma unroll 1
    for (int i = 0; i < 16; i++) {
        float ci0 = sl0[i] * shs0, ci1 = sl1[i] * shs1;
        const float* wb = sW2 + (i * 16) * 32;
        const float* bb = sB2 + i * 16;
#pragma unroll
        for (int o = 0; o < 16; o++) {
            float a0, a1;
            dot2e(wb + o * 32, h0, h1, a0, a1);
            float b = bb[o];
            os0[o] = fmaf(ci0, a0 + b, os0[o]);
            os1[o] = fmaf(ci1, a1 + b, os1[o]);
        }
    }
#pragma unroll 1
    for (int i = 0; i < 8; i++) {
        float ci0 = sl0[16 + i], ci1 = sl1[16 + i];
        const float* wb = sW2 + (256 + i * 16) * 32;
        const float* bb = sB2 + 256 + i * 16;
#pragma unroll
        for (int o = 0; o < 16; o++) {
            float a0, a1;
            dot2e(wb + o * 32, h0, h1, a0, a1);
            float b = bb[o];
            os0[o] = fmaf(ci0, a0 + b, os0[o]);
            os1[o] = fmaf(ci1, a1 + b, os1[o]);
        }
    }
}

// Phase B1: block 3 (cols 384..511); tile holds cols 384.. at base 0.
__device__ __forceinline__ void phaseB1(const float* __restrict__ sW2, const float* __restrict__ sB2,
                                        const u64 (&h0)[16], const u64 (&h1)[16],
                                        const float* __restrict__ sl0, const float* __restrict__ sl1,
                                        float s00, float s01, float s02,
                                        float s10, float s11, float s12,
                                        float (&ov0)[24], float (&ov1)[24]) {
#pragma unroll 1
    for (int i = 0; i < 16; i++) {
        float ci0 = sl0[i], ci1 = sl1[i];
        const float* wb = sW2 + (i * 8) * 32;
        const float* bb = sB2 + 384 + i * 8;
#pragma unroll
        for (int o = 0; o < 8; o++) {
            float a0, a1;
            dot2e(wb + o * 32, h0, h1, a0, a1);
            float b = bb[o];
            float t0 = ci0 * (a0 + b), t1 = ci1 * (a1 + b);
            ov0[o * 3 + 0] = fmaf(t0, s00, ov0[o * 3 + 0]);
            ov0[o * 3 + 1] = fmaf(t0, s01, ov0[o * 3 + 1]);
            ov0[o * 3 + 2] = fmaf(t0, s02, ov0[o * 3 + 2]);
            ov1[o * 3 + 0] = fmaf(t1, s10, ov1[o * 3 + 0]);
            ov1[o * 3 + 1] = fmaf(t1, s11, ov1[o * 3 + 1]);
            ov1[o * 3 + 2] = fmaf(t1, s12, ov1[o * 3 + 2]);
        }
    }
}

// Phase B2: blocks 4 (cols 512..575) and 5 (576..639); tile holds cols 512.. at base 0.
__device__ __forceinline__ void phaseB2(const float* __restrict__ sW2, const float* __restrict__ sB2,
                                        const u64 (&h0)[16], const u64 (&h1)[16],
                                        const float* __restrict__ sl0, const float* __restrict__ sl1,
                                        float shs0, float shs1,
                                        float (&ov0)[24], float (&ov1)[24]) {
#pragma unroll 1
    for (int i = 0; i < 8; i++) {
        const float* wb = sW2 + (i * 8) * 32;
        const float* bb = sB2 + 512 + i * 8;
        float x00 = sl0[i * 3 + 0], x01 = sl0[i * 3 + 1], x02 = sl0[i * 3 + 2];
        float x10 = sl1[i * 3 + 0], x11 = sl1[i * 3 + 1], x12 = sl1[i * 3 + 2];
#pragma unroll
        for (int o = 0; o < 8; o++) {
            float a0, a1;
            dot2e(wb + o * 32, h0, h1, a0, a1);
            float b = bb[o];
            float t0 = shs0 * (a0 + b), t1 = shs1 * (a1 + b);
            ov0[o * 3 + 0] = fmaf(t0, x00, ov0[o * 3 + 0]);
            ov0[o * 3 + 1] = fmaf(t0, x01, ov0[o * 3 + 1]);
            ov0[o * 3 + 2] = fmaf(t0, x02, ov0[o * 3 + 2]);
            ov1[o * 3 + 0] = fmaf(t1, x10, ov1[o * 3 + 0]);
            ov1[o * 3 + 1] = fmaf(t1, x11, ov1[o * 3 + 1]);
            ov1[o * 3 + 2] = fmaf(t1, x12, ov1[o * 3 + 2]);
        }
    }
#pragma unroll 1
    for (int i = 0; i < 8; i++) {
        const float* wb = sW2 + (64 + i * 8) * 32;
        const float* bb = sB2 + 576 + i * 8;
        float c00 = sl0[24 + i * 3 + 0], c01 = sl0[24 + i * 3 + 1], c02 = sl0[24 + i * 3 + 2];
        float c10 = sl1[24 + i * 3 + 0], c11 = sl1[24 + i * 3 + 1], c12 = sl1[24 + i * 3 + 2];
#pragma unroll
        for (int o = 0; o < 8; o++) {
            float a0, a1;
            dot2e(wb + o * 32, h0, h1, a0, a1);
            float b = bb[o];
            a0 += b; a1 += b;
            ov0[o * 3 + 0] = fmaf(a0, c00, ov0[o * 3 + 0]);
            ov0[o * 3 + 1] = fmaf(a0, c01, ov0[o * 3 + 1]);
            ov0[o * 3 + 2] = fmaf(a0, c02, ov0[o * 3 + 2]);
            ov1[o * 3 + 0] = fmaf(a1, c10, ov1[o * 3 + 0]);
            ov1[o * 3 + 1] = fmaf(a1, c11, ov1[o * 3 + 1]);
            ov1[o * 3 + 2] = fmaf(a1, c12, ov1[o * 3 + 2]);
        }
    }
}

// ---------------- smem layout (floats) ----------------
#define SM_W2    0                    /* tile: up to 12288 floats */
#define SM_W1K   12288
#define SM_W1V   (SM_W1K + 1024)
#define SM_B1K   (SM_W1V + 1024)
#define SM_B1V   (SM_B1K + 32)
#define SM_B2K   (SM_B1V + 32)
#define SM_B2V   (SM_B2K + 640)
#define SM_SLAB  (SM_B2V + 640)       /* 128 threads x 97 floats */
#define SM_TOTAL (SM_SLAB + 128 * 97)
#define SMEM_BYTES (SM_TOTAL * 4)

#define TILE_A_F4   3072   /* cols 0..383   (12288 floats) */
#define TILE_B_F4   1024   /* cols .. +128  (4096 floats)  */

__device__ __forceinline__ void copy_tile(float* __restrict__ dst, const float* __restrict__ src,
                                          int nf4, int tid) {
    const float4* s = (const float4*)src;
    float4* d = (float4*)dst;
    for (int i = tid; i < nf4; i += 128) d[i] = s[i];
}

__global__ __launch_bounds__(128, 2) void k_edges(
    const float* __restrict__ atom, const float* __restrict__ ef_g,
    const float* __restrict__ sh_g, const int* __restrict__ eidx,
    const float* __restrict__ kw1, const float* __restrict__ kb1, const float* __restrict__ kb2,
    const float* __restrict__ vw1, const float* __restrict__ vb1, const float* __restrict__ vb2) {
    extern __shared__ float sm[];
    float* sW2  = sm + SM_W2;
    float* sW1k = sm + SM_W1K;
    float* sW1v = sm + SM_W1V;
    float* sB1k = sm + SM_B1K;
    float* sB1v = sm + SM_B1V;
    float* sB2k = sm + SM_B2K;
    float* sB2v = sm + SM_B2V;
    int tid = threadIdx.x;
    float* sl0 = sm + SM_SLAB + tid * 97;
    float* sl1 = sl0 + 48;
    __shared__ int sTicket;

    // one-time staging of W1 (transposed) and biases
    for (int i = tid; i < 1024; i += 128) {
        sW1k[(i % 32) * 32 + (i / 32)] = kw1[i];
        sW1v[(i % 32) * 32 + (i / 32)] = vw1[i];
    }
    for (int i = tid; i < 640; i += 128) { sB2k[i] = kb2[i]; sB2v[i] = vb2[i]; }
    if (tid < 32) { sB1k[tid] = kb1[tid]; sB1v[tid] = vb1[tid]; }

    for (;;) {
        __syncthreads();  // prior chunk complete; W1/bias staging visible on first pass
        if (tid == 0) sTicket = atomicAdd(&g_ticket, 1);
        __syncthreads();
        int chunk = sTicket;
        if (chunk >= NCHUNK) break;

        int e0 = chunk * CHUNK + tid;
        int e1 = e0 + 128;

        int dst0 = __ldg(eidx + e0), dst1 = __ldg(eidx + e1);
        int src0 = __ldg(eidx + N_EDGES + e0), src1 = __ldg(eidx + N_EDGES + e1);
        float4 sh40 = __ldg(((const float4*)sh_g) + e0);
        float4 sh41 = __ldg(((const float4*)sh_g) + e1);

        u64 h2a[16], h2b[16];
        float os0[16], os1[16], ov0[24], ov1[24];

        // ================= K path =================
        copy_tile(sW2, g_W2kT, TILE_A_F4, tid);
        __syncthreads();
        mlp1_2(sW1k, sB1k, ef_g, e0, e1, h2a, h2b);
        write_slabA(atom, dst0, sl0, sh40.y, sh40.z, sh40.w);
        write_slabA(atom, dst1, sl1, sh41.y, sh41.z, sh41.w);
#pragma unroll
        for (int o = 0; o < 16; o++) { os0[o] = 0.0f; os1[o] = 0.0f; }
#pragma unroll
        for (int t = 0; t < 24; t++) { ov0[t] = 0.0f; ov1[t] = 0.0f; }
        phaseA(sW2, sB2k, h2a, h2b, sl0, sl1, sh40.x, sh41.x, os0, os1);

        __syncthreads();
        copy_tile(sW2, g_W2kT + 12288, TILE_B_F4, tid);
        __syncthreads();
        phaseB1(sW2, sB2k, h2a, h2b, sl0, sl1,
                sh40.y, sh40.z, sh40.w, sh41.y, sh41.z, sh41.w, ov0, ov1);

        __syncthreads();
        copy_tile(sW2, g_W2kT + 16384, TILE_B_F4, tid);
        __syncthreads();
        write_slabB(atom, dst0, sl0, sh40.y, sh40.z, sh40.w);
        write_slabB(atom, dst1, sl1, sh41.y, sh41.z, sh41.w);
        phaseB2(sW2, sB2k, h2a, h2b, sl0, sl1, sh40.x, sh41.x, ov0, ov1);

        // attention logits
        {
            float qv[40];
            const float4* q = (const float4*)(g_q + (size_t)src0 * 40);
#pragma unroll
            for (int i = 0; i < 10; i++) {
                float4 v = __ldg(q + i);
                qv[4 * i] = v.x; qv[4 * i + 1] = v.y; qv[4 * i + 2] = v.z; qv[4 * i + 3] = v.w;
            }
            float attn = 0.0f;
#pragma unroll
            for (int o = 0; o < 16; o++) attn = fmaf(os0[o], qv[o], attn);
#pragma unroll
            for (int t = 0; t < 24; t++) attn = fmaf(ov0[t], qv[16 + t], attn);
            g_attn[e0] = attn;
            atomicMax(&g_m[src0], fkey(attn));
        }
        {
            float qv[40];
            const float4* q = (const float4*)(g_q + (size_t)src1 * 40);
#pragma unroll
            for (int i = 0; i < 10; i++) {
                float4 v = __ldg(q + i);
                qv[4 * i] = v.x; qv[4 * i + 1] = v.y; qv[4 * i + 2] = v.z; qv[4 * i + 3] = v.w;
            }
            float attn = 0.0f;
#pragma unroll
            for (int o = 0; o < 16; o++) attn = fmaf(os1[o], qv[o], attn);
#pragma unroll
            for (int t = 0; t < 24; t++) attn = fmaf(ov1[t], qv[16 + t], attn);
            g_attn[e1] = attn;
            atomicMax(&g_m[src1], fkey(attn));
        }

        // ================= V path =================
        __syncthreads();
        copy_tile(sW2, g_W2vT, TILE_A_F4, tid);
        __syncthreads();
        mlp1_2(sW1v, sB1v, ef_g, e0, e1, h2a, h2b);
        write_slabA(atom, dst0, sl0, sh40.y, sh40.z, sh40.w);
        write_slabA(atom, dst1, sl1, sh41.y, sh41.z, sh41.w);
#pragma unroll
        for (int o = 0; o < 16; o++) { os0[o] = 0.0f; os1[o] = 0.0f; }
#pragma unroll
        for (int t = 0; t < 24; t++) { ov0[t] = 0.0f; ov1[t] = 0.0f; }
        phaseA(sW2, sB2v, h2a, h2b, sl0, sl1, sh40.x, sh41.x, os0, os1);

        __syncthreads();
        copy_tile(sW2, g_W2vT + 12288, TILE_B_F4, tid);
        __syncthreads();
        phaseB1(sW2, sB2v, h2a, h2b, sl0, sl1,
                sh40.y, sh40.z, sh40.w, sh41.y, sh41.z, sh41.w, ov0, ov1);

        __syncthreads();
        copy_tile(sW2, g_W2vT + 16384, TILE_B_F4, tid);
        __syncthreads();
        write_slabB(atom, dst0, sl0, sh40.y, sh40.z, sh40.w);
        write_slabB(atom, dst1, sl1, sh41.y, sh41.z, sh41.w);
        phaseB2(sW2, sB2v, h2a, h2b, sl0, sl1, sh40.x, sh41.x, ov0, ov1);

#pragma unroll
        for (int o = 0; o < 16; o++) {
            g_vT[(size_t)o * N_EDGES + e0] = os0[o];
            g_vT[(size_t)o * N_EDGES + e1] = os1[o];
        }
#pragma unroll
        for (int t = 0; t < 24; t++) {
            g_vT[(size_t)(16 + t) * N_EDGES + e0] = ov0[t];
            g_vT[(size_t)(16 + t) * N_EDGES + e1] = ov1[t];
        }
    }
}

// ---------------- softmax accumulation ----------------
__global__ void k_soft(const int* __restrict__ eidx) {
    int e = blockIdx.x * 256 + threadIdx.x;
    if (e >= N_EDGES) return;
    int src = eidx[N_EDGES + e];
    float m = fdec(g_m[src]);
    float ex = expf(g_attn[e] - m);
    atomicAdd(&g_denom[src], ex);
#pragma unroll
    for (int f = 0; f < 40; f++) {
        atomicAdd(&g_numer[f * N_NODES + src], ex * g_vT[(size_t)f * N_EDGES + e]);
    }
}

// ---------------- pre-activation + batchnorm stats ----------------
__global__ void k_stats(const float* __restrict__ atom) {
    int f = blockIdx.y;
    int n = blockIdx.x * 256 + threadIdx.x;
    float pre = 0.0f;
    if (n < N_NODES) {
        float den = g_denom[n];
        float upd = (den > 0.0f) ? g_numer[f * N_NODES + n] / den : 0.0f;
        pre = atom[(size_t)n * 40 + f] + upd;
        g_pre[f * N_NODES + n] = pre;
    }
    float s = pre, ss = pre * pre;
    unsigned lane = threadIdx.x & 31, wid = threadIdx.x >> 5;
#pragma unroll
    for (int o = 16; o > 0; o >>= 1) {
        s += __shfl_down_sync(0xFFFFFFFFu, s, o);
        ss += __shfl_down_sync(0xFFFFFFFFu, ss, o);
    }
    __shared__ float rs[8], rss[8];
    if (lane == 0) { rs[wid] = s; rss[wid] = ss; }
    __syncthreads();
    if (threadIdx.x == 0) {
        float S = 0.0f, SS = 0.0f;
#pragma unroll
        for (int w = 0; w < 8; w++) { S += rs[w]; SS += rss[w]; }
        atomicAdd(&g_stats[f], S);
        atomicAdd(&g_stats[40 + f], SS);
    }
}

// ---------------- batchnorm finalize ----------------
__global__ void k_final(const float* __restrict__ bnws, const float* __restrict__ bnbs,
                        const float* __restrict__ bnwv, float* __restrict__ out) {
    int t = blockIdx.x * 256 + threadIdx.x;
    if (t >= 40 * N_NODES) return;
    int n = t / 40, f = t % 40;
    float pre = g_pre[f * N_NODES + n];
    float r;
    if (f < 16) {
        float mu = g_stats[f] * (1.0f / N_NODES);
        float var = g_stats[40 + f] * (1.0f / N_NODES) - mu * mu;
        r = (pre - mu) * rsqrtf(var + 1e-5f) * bnws[f] + bnbs[f];
    } else {
        int i = (f - 16) / 3;
        float nrm = (g_stats[40 + 16 + i * 3 + 0] + g_stats[40 + 16 + i * 3 + 1] +
                     g_stats[40 + 16 + i * 3 + 2]) * (1.0f / (3.0f * N_NODES));
        r = pre * rsqrtf(nrm + 1e-5f) * bnwv[i];
    }
    out[t] = r;
}

// ---------------- passthrough copy of edge_features ----------------
__global__ void k_copyef(const float* __restrict__ ef, float* __restrict__ out) {
    int t = blockIdx.x * 256 + threadIdx.x;
    if (t >= (N_EDGES * 32) / 4) return;
    ((float4*)out)[t] = ((const float4*)ef)[t];
}

// ---------------- launch ----------------
extern "C" void kernel_launch(void* const* d_in, const int* in_sizes, int n_in,
                              void* d_out, int out_size) {
    const float* atom = (const float*)d_in[0];
    const float* ef   = (const float*)d_in[1];
    const float* sh   = (const float*)d_in[2];
    const float* Wq_s = (const float*)d_in[3];
    const float* Wq_v = (const float*)d_in[4];
    const float* kw1  = (const float*)d_in[5];
    const float* kb1  = (const float*)d_in[6];
    const float* kw2  = (const float*)d_in[7];
    const float* kb2  = (const float*)d_in[8];
    const float* vw1  = (const float*)d_in[9];
    const float* vb1  = (const float*)d_in[10];
    const float* vw2  = (const float*)d_in[11];
    const float* vb2  = (const float*)d_in[12];
    const float* bnws = (const float*)d_in[13];
    const float* bnbs = (const float*)d_in[14];
    const float* bnwv = (const float*)d_in[15];
    const int*   eidx = (const int*)d_in[16];
    float* out = (float*)d_out;

    cudaFuncSetAttribute(k_edges, cudaFuncAttributeMaxDynamicSharedMemorySize, SMEM_BYTES);

    k_init<<<(40 * N_NODES + 255) / 256, 256>>>();
    k_transpose<<<(WN * 32 + 255) / 256, 256>>>(kw2, vw2);
    k_q<<<(40 * N_NODES + 255) / 256, 256>>>(atom, Wq_s, Wq_v);
    k_edges<<<EGRID, 128, SMEM_BYTES>>>(atom, ef, sh, eidx,
                                        kw1, kb1, kb2, vw1, vb1, vb2);
    k_soft<<<(N_EDGES + 255) / 256, 256>>>(eidx);
    dim3 gs((N_NODES + 255) / 256, 40);
    k_stats<<<gs, 256>>>(atom);
    k_final<<<(40 * N_NODES + 255) / 256, 256>>>(bnws, bnbs, bnwv, out);
    k_copyef<<<((N_EDGES * 32) / 4 + 255) / 256, 256>>>(ef, out + 40 * N_NODES);
}

// round 5
// speedup vs baseline: 1.0926x; 1.0926x over previous
#include <cuda_runtime.h>
#include <math.h>

#define N_NODES 10000
#define N_EDGES 160000
#define WN 640
#define C110 0.57735026918962576451f   /* 1/sqrt(3) */
#define C111 0.70710678118654752440f   /* 1/sqrt(2) */

#define CHUNK 256                      /* edges per chunk: 128 threads x 2 edges */
#define NCHUNK (N_EDGES / CHUNK)       /* 625, exact */
#define EGRID 444                      /* persistent CTAs (3 per SM) */

typedef unsigned long long u64;

// ---------------- device scratch ----------------
__device__ float g_W2kT[WN * 32];
__device__ float g_W2vT[WN * 32];
__device__ float g_q[N_NODES * 40];
__device__ float g_attn[N_EDGES];
__device__ float g_vT[40 * (size_t)N_EDGES];
__device__ int   g_m[N_NODES];
__device__ float g_denom[N_NODES];
__device__ float g_numer[40 * N_NODES];
__device__ float g_pre[40 * N_NODES];
__device__ float g_stats[80];
__device__ int   g_ticket;

// ---------------- packed f32x2 helpers ----------------
__device__ __forceinline__ u64 fma2(u64 a, u64 b, u64 c) {
    u64 d;
    asm("fma.rn.f32x2 %0, %1, %2, %3;" : "=l"(d) : "l"(a), "l"(b), "l"(c));
    return d;
}
__device__ __forceinline__ u64 pack2(float lo, float hi) {
    u64 r;
    asm("mov.b64 %0, {%1, %2};" : "=l"(r) : "f"(lo), "f"(hi));
    return r;
}
__device__ __forceinline__ float sum2(u64 v) {
    float a, b;
    asm("mov.b64 {%0, %1}, %2;" : "=f"(a), "=f"(b) : "l"(v));
    return a + b;
}

__device__ __forceinline__ int fkey(float f) {
    int b = __float_as_int(f);
    return (b >= 0) ? b : (int)(b ^ 0x7FFFFFFF);
}
__device__ __forceinline__ float fdec(int k) {
    return (k >= 0) ? __int_as_float(k) : __int_as_float((int)(k ^ 0x7FFFFFFF));
}

// ---------------- prep kernels ----------------
__global__ void k_init() {
    int i = blockIdx.x * 256 + threadIdx.x;
    if (i < 40 * N_NODES) g_numer[i] = 0.0f;
    if (i < N_NODES) { g_denom[i] = 0.0f; g_m[i] = (int)0x807FFFFFu; }
    if (i < 80) g_stats[i] = 0.0f;
    if (i == 0) g_ticket = 0;
}

__global__ void k_transpose(const float* __restrict__ kw2, const float* __restrict__ vw2) {
    int i = blockIdx.x * 256 + threadIdx.x;
    if (i < WN * 32) {
        int j = i / WN, c = i % WN;
        g_W2kT[c * 32 + j] = kw2[i];
        g_W2vT[c * 32 + j] = vw2[i];
    }
}

__global__ void k_q(const float* __restrict__ atom, const float* __restrict__ Wqs,
                    const float* __restrict__ Wqv) {
    int t = blockIdx.x * 256 + threadIdx.x;
    if (t >= 40 * N_NODES) return;
    int n = t / 40, f = t % 40;
    const float* a = atom + (size_t)n * 40;
    float acc = 0.0f;
    if (f < 16) {
#pragma unroll
        for (int i = 0; i < 16; i++) acc = fmaf(a[i], Wqs[i * 16 + f], acc);
    } else {
        int o = (f - 16) / 3, d = (f - 16) % 3;
#pragma unroll
        for (int i = 0; i < 8; i++) acc = fmaf(a[16 + i * 3 + d], Wqv[i * 8 + o], acc);
    }
    g_q[t] = acc;
}

// ---------------- shared 2-edge dot over one 32-wide column ----------------
__device__ __forceinline__ void dot2e(const float* __restrict__ w,
                                      const u64 (&ha)[16], const u64 (&hb)[16],
                                      float& r0, float& r1) {
    const ulonglong2* wp = (const ulonglong2*)w;
    u64 a0 = 0, b0 = 0, a1 = 0, b1 = 0;
#pragma unroll
    for (int j = 0; j < 4; j++) {
        ulonglong2 w1 = wp[2 * j], w2 = wp[2 * j + 1];
        a0 = fma2(ha[4 * j + 0], w1.x, a0);
        b0 = fma2(ha[4 * j + 1], w1.y, b0);
        a0 = fma2(ha[4 * j + 2], w2.x, a0);
        b0 = fma2(ha[4 * j + 3], w2.y, b0);
        a1 = fma2(hb[4 * j + 0], w1.x, a1);
        b1 = fma2(hb[4 * j + 1], w1.y, b1);
        a1 = fma2(hb[4 * j + 2], w2.x, a1);
        b1 = fma2(hb[4 * j + 3], w2.y, b1);
    }
    r0 = sum2(a0) + sum2(b0);
    r1 = sum2(a1) + sum2(b1);
}

// ---------------- MLP layer-1 for two edges ----------------
__device__ __forceinline__ void load_ef2(const float* __restrict__ ef_g, int e, u64 (&ef2)[16]) {
    const float4* p = (const float4*)(ef_g + (size_t)e * 32);
#pragma unroll
    for (int i = 0; i < 8; i++) {
        float4 v = __ldg(p + i);
        ef2[2 * i + 0] = pack2(v.x, v.y);
        ef2[2 * i + 1] = pack2(v.z, v.w);
    }
}

__device__ __forceinline__ void mlp1_2(const float* __restrict__ sW1T,
                                       const float* __restrict__ sB1,
                                       const float* __restrict__ ef_g, int e0, int e1,
                                       u64 (&h2a)[16], u64 (&h2b)[16]) {
    u64 efa[16], efb[16];
    load_ef2(ef_g, e0, efa);
    load_ef2(ef_g, e1, efb);
#pragma unroll 1
    for (int c = 0; c < 16; c++) {
        float r0a, r0b, r1a, r1b;
        dot2e(sW1T + (2 * c) * 32, efa, efb, r0a, r0b);
        dot2e(sW1T + (2 * c + 1) * 32, efa, efb, r1a, r1b);
        float b0 = sB1[2 * c], b1 = sB1[2 * c + 1];
        h2a[c] = pack2(fmaxf(r0a + b0, 0.0f), fmaxf(r1a + b1, 0.0f));
        h2b[c] = pack2(fmaxf(r0b + b0, 0.0f), fmaxf(r1b + b1, 0.0f));
    }
}

// ---------------- coefficient slab writers ----------------
// slabA per edge (24 floats): [0..15]=x_s, [16..23]=C110*dot(x_v, sh_v)
__device__ __forceinline__ void write_slabA(const float* __restrict__ atom, int node,
                                            float* __restrict__ sl,
                                            float s0, float s1, float s2) {
    const float4* p = (const float4*)(atom + (size_t)node * 40);
#pragma unroll
    for (int i = 0; i < 4; i++) {
        float4 v = __ldg(p + i);
        sl[4 * i + 0] = v.x; sl[4 * i + 1] = v.y; sl[4 * i + 2] = v.z; sl[4 * i + 3] = v.w;
    }
    float xv[24];
#pragma unroll
    for (int i = 0; i < 6; i++) {
        float4 v = __ldg(p + 4 + i);
        xv[4 * i + 0] = v.x; xv[4 * i + 1] = v.y; xv[4 * i + 2] = v.z; xv[4 * i + 3] = v.w;
    }
#pragma unroll
    for (int i = 0; i < 8; i++)
        sl[16 + i] = C110 * (xv[3 * i] * s0 + xv[3 * i + 1] * s1 + xv[3 * i + 2] * s2);
}

// slabB per edge (48 floats): [0..23]=x_v, [24..47]=C111*cross(x_v, sh_v)
__device__ __forceinline__ void write_slabB(const float* __restrict__ atom, int node,
                                            float* __restrict__ sl,
                                            float s0, float s1, float s2) {
    const float4* p = (const float4*)(atom + (size_t)node * 40);
    float xv[24];
#pragma unroll
    for (int i = 0; i < 6; i++) {
        float4 v = __ldg(p + 4 + i);
        xv[4 * i + 0] = v.x; xv[4 * i + 1] = v.y; xv[4 * i + 2] = v.z; xv[4 * i + 3] = v.w;
    }
#pragma unroll
    for (int i = 0; i < 8; i++) {
        float a0 = xv[3 * i], a1 = xv[3 * i + 1], a2 = xv[3 * i + 2];
        sl[i * 3 + 0] = a0; sl[i * 3 + 1] = a1; sl[i * 3 + 2] = a2;
        sl[24 + i * 3 + 0] = C111 * (a1 * s2 - a2 * s1);
        sl[24 + i * 3 + 1] = C111 * (a2 * s0 - a0 * s2);
        sl[24 + i * 3 + 2] = C111 * (a0 * s1 - a1 * s0);
    }
}

// ---------------- per-tile GEMM+fold workers (128 cols/tile) ----------------
// 16-output tile (blocks 1/2): k-path folds into attn, v-path into os.
__device__ __forceinline__ void tile16_attn(const float* __restrict__ sW2,
                                            const float* __restrict__ b2g,
                                            const u64 (&h0)[16], const u64 (&h1)[16],
                                            const float (&cf0)[8], const float (&cf1)[8],
                                            const float (&qs0)[16], const float (&qs1)[16],
                                            float& attn0, float& attn1) {
#pragma unroll 1
    for (int g = 0; g < 8; g++) {
        const float* wb = sW2 + g * 16 * 32;
        float c0 = cf0[g], c1 = cf1[g];
#pragma unroll
        for (int o = 0; o < 16; o++) {
            float a0, a1;
            dot2e(wb + o * 32, h0, h1, a0, a1);
            float b = __ldg(b2g + g * 16 + o);
            attn0 = fmaf(c0 * (a0 + b), qs0[o], attn0);
            attn1 = fmaf(c1 * (a1 + b), qs1[o], attn1);
        }
    }
}

__device__ __forceinline__ void tile16_os(const float* __restrict__ sW2,
                                          const float* __restrict__ b2g,
                                          const u64 (&h0)[16], const u64 (&h1)[16],
                                          const float (&cf0)[8], const float (&cf1)[8],
                                          float (&os0)[16], float (&os1)[16]) {
#pragma unroll 1
    for (int g = 0; g < 8; g++) {
        const float* wb = sW2 + g * 16 * 32;
        float c0 = cf0[g], c1 = cf1[g];
#pragma unroll
        for (int o = 0; o < 16; o++) {
            float a0, a1;
            dot2e(wb + o * 32, h0, h1, a0, a1);
            float b = __ldg(b2g + g * 16 + o);
            os0[o] = fmaf(c0, a0 + b, os0[o]);
            os1[o] = fmaf(c1, a1 + b, os1[o]);
        }
    }
}

// Tile 3 (block 3, cols 384..511): 16 i-groups x 8 outputs; coef = x_s[i] (slab), times sh_v.
__device__ __forceinline__ void tileT3(const float* __restrict__ sW2,
                                       const float* __restrict__ b2g,
                                       const u64 (&h0)[16], const u64 (&h1)[16],
                                       const float* __restrict__ sl0, const float* __restrict__ sl1,
                                       float s00, float s01, float s02,
                                       float s10, float s11, float s12,
                                       float (&ov0)[24], float (&ov1)[24]) {
#pragma unroll 1
    for (int i = 0; i < 16; i++) {
        float ci0 = sl0[i], ci1 = sl1[i];
        const float* wb = sW2 + i * 8 * 32;
#pragma unroll
        for (int o = 0; o < 8; o++) {
            float a0, a1;
            dot2e(wb + o * 32, h0, h1, a0, a1);
            float b = __ldg(b2g + i * 8 + o);
            float t0 = ci0 * (a0 + b), t1 = ci1 * (a1 + b);
            ov0[o * 3 + 0] = fmaf(t0, s00, ov0[o * 3 + 0]);
            ov0[o * 3 + 1] = fmaf(t0, s01, ov0[o * 3 + 1]);
            ov0[o * 3 + 2] = fmaf(t0, s02, ov0[o * 3 + 2]);
            ov1[o * 3 + 0] = fmaf(t1, s10, ov1[o * 3 + 0]);
            ov1[o * 3 + 1] = fmaf(t1, s11, ov1[o * 3 + 1]);
            ov1[o * 3 + 2] = fmaf(t1, s12, ov1[o * 3 + 2]);
        }
    }
}

// Tile 4 (blocks 4+5, cols 512..639): slab holds xv[0..23], cross[24..47].
__device__ __forceinline__ void tileT4(const float* __restrict__ sW2,
                                       const float* __restrict__ b2g,
                                       const u64 (&h0)[16], const u64 (&h1)[16],
                                       const float* __restrict__ sl0, const float* __restrict__ sl1,
                                       float shs0, float shs1,
                                       float (&ov0)[24], float (&ov1)[24]) {
#pragma unroll 1
    for (int i = 0; i < 8; i++) {
        const float* wb = sW2 + i * 8 * 32;
        float x00 = sl0[i * 3 + 0], x01 = sl0[i * 3 + 1], x02 = sl0[i * 3 + 2];
        float x10 = sl1[i * 3 + 0], x11 = sl1[i * 3 + 1], x12 = sl1[i * 3 + 2];
#pragma unroll
        for (int o = 0; o < 8; o++) {
            float a0, a1;
            dot2e(wb + o * 32, h0, h1, a0, a1);
            float b = __ldg(b2g + i * 8 + o);
            float t0 = shs0 * (a0 + b), t1 = shs1 * (a1 + b);
            ov0[o * 3 + 0] = fmaf(t0, x00, ov0[o * 3 + 0]);
            ov0[o * 3 + 1] = fmaf(t0, x01, ov0[o * 3 + 1]);
            ov0[o * 3 + 2] = fmaf(t0, x02, ov0[o * 3 + 2]);
            ov1[o * 3 + 0] = fmaf(t1, x10, ov1[o * 3 + 0]);
            ov1[o * 3 + 1] = fmaf(t1, x11, ov1[o * 3 + 1]);
            ov1[o * 3 + 2] = fmaf(t1, x12, ov1[o * 3 + 2]);
        }
    }
#pragma unroll 1
    for (int i = 0; i < 8; i++) {
        const float* wb = sW2 + (64 + i * 8) * 32;
        float c00 = sl0[24 + i * 3 + 0], c01 = sl0[24 + i * 3 + 1], c02 = sl0[24 + i * 3 + 2];
        float c10 = sl1[24 + i * 3 + 0], c11 = sl1[24 + i * 3 + 1], c12 = sl1[24 + i * 3 + 2];
#pragma unroll
        for (int o = 0; o < 8; o++) {
            float a0, a1;
            dot2e(wb + o * 32, h0, h1, a0, a1);
            float b = __ldg(b2g + 64 + i * 8 + o);
            a0 += b; a1 += b;
            ov0[o * 3 + 0] = fmaf(a0, c00, ov0[o * 3 + 0]);
            ov0[o * 3 + 1] = fmaf(a0, c01, ov0[o * 3 + 1]);
            ov0[o * 3 + 2] = fmaf(a0, c02, ov0[o * 3 + 2]);
            ov1[o * 3 + 0] = fmaf(a1, c10, ov1[o * 3 + 0]);
            ov1[o * 3 + 1] = fmaf(a1, c11, ov1[o * 3 + 1]);
            ov1[o * 3 + 2] = fmaf(a1, c12, ov1[o * 3 + 2]);
        }
    }
}

// ---------------- smem layout (floats) ----------------
#define SM_W2    0                    /* 128-col tile: 4096 floats (16KB) */
#define SM_W1K   4096
#define SM_W1V   (SM_W1K + 1024)
#define SM_B1K   (SM_W1V + 1024)
#define SM_B1V   (SM_B1K + 32)
#define SM_SLAB  (SM_B1V + 32)        /* 128 threads x 97 floats */
#define SM_TOTAL (SM_SLAB + 128 * 97)
#define SMEM_BYTES (SM_TOTAL * 4)     /* 74496 bytes -> 3 CTAs/SM */

#define TILE_F4 1024                  /* 4096 floats per tile */

__device__ __forceinline__ void copy_tile(float* __restrict__ dst, const float* __restrict__ src,
                                          int tid) {
    const float4* s = (const float4*)src;
    float4* d = (float4*)dst;
#pragma unroll
    for (int k = 0; k < 8; k++) d[tid + 128 * k] = s[tid + 128 * k];
}

__global__ __launch_bounds__(128, 3) void k_edges(
    const float* __restrict__ atom, const float* __restrict__ ef_g,
    const float* __restrict__ sh_g, const int* __restrict__ eidx,
    const float* __restrict__ kw1, const float* __restrict__ kb1, const float* __restrict__ kb2,
    const float* __restrict__ vw1, const float* __restrict__ vb1, const float* __restrict__ vb2) {
    extern __shared__ float sm[];
    float* sW2  = sm + SM_W2;
    float* sW1k = sm + SM_W1K;
    float* sW1v = sm + SM_W1V;
    float* sB1k = sm + SM_B1K;
    float* sB1v = sm + SM_B1V;
    int tid = threadIdx.x;
    float* sl0 = sm + SM_SLAB + tid * 97;
    float* sl1 = sl0 + 48;
    __shared__ int sTicket;

    // one-time staging of W1 (transposed) + layer-1 biases
    for (int i = tid; i < 1024; i += 128) {
        sW1k[(i % 32) * 32 + (i / 32)] = kw1[i];
        sW1v[(i % 32) * 32 + (i / 32)] = vw1[i];
    }
    if (tid < 32) { sB1k[tid] = kb1[tid]; sB1v[tid] = vb1[tid]; }

    for (;;) {
        __syncthreads();  // prior chunk's last tile use done; staging visible first pass
        if (tid == 0) sTicket = atomicAdd(&g_ticket, 1);
        __syncthreads();
        int chunk = sTicket;
        if (chunk >= NCHUNK) break;

        int e0 = chunk * CHUNK + tid;
        int e1 = e0 + 128;

        int dst0 = __ldg(eidx + e0), dst1 = __ldg(eidx + e1);
        int src0 = __ldg(eidx + N_EDGES + e0), src1 = __ldg(eidx + N_EDGES + e1);
        float4 sh40 = __ldg(((const float4*)sh_g) + e0);
        float4 sh41 = __ldg(((const float4*)sh_g) + e1);

        u64 h2a[16], h2b[16];
        float ov0[24], ov1[24];

        // ======================= K path =======================
        copy_tile(sW2, g_W2kT, tid);
        mlp1_2(sW1k, sB1k, ef_g, e0, e1, h2a, h2b);
        write_slabA(atom, dst0, sl0, sh40.y, sh40.z, sh40.w);
        write_slabA(atom, dst1, sl1, sh41.y, sh41.z, sh41.w);

        float attn0 = 0.0f, attn1 = 0.0f;
        {
            // q_s for both source nodes
            float qs0[16], qs1[16];
            {
                const float4* q = (const float4*)(g_q + (size_t)src0 * 40);
#pragma unroll
                for (int i = 0; i < 4; i++) {
                    float4 v = __ldg(q + i);
                    qs0[4 * i] = v.x; qs0[4 * i + 1] = v.y; qs0[4 * i + 2] = v.z; qs0[4 * i + 3] = v.w;
                }
                const float4* p = (const float4*)(g_q + (size_t)src1 * 40);
#pragma unroll
                for (int i = 0; i < 4; i++) {
                    float4 v = __ldg(p + i);
                    qs1[4 * i] = v.x; qs1[4 * i + 1] = v.y; qs1[4 * i + 2] = v.z; qs1[4 * i + 3] = v.w;
                }
            }
            float cf0[8], cf1[8];
            __syncthreads();  // tile0 ready
            // T0: block1 i=0..7
#pragma unroll
            for (int g = 0; g < 8; g++) { cf0[g] = sl0[g] * sh40.x; cf1[g] = sl1[g] * sh41.x; }
            tile16_attn(sW2, kb2, h2a, h2b, cf0, cf1, qs0, qs1, attn0, attn1);
            __syncthreads();
            copy_tile(sW2, g_W2kT + 4096, tid);
            __syncthreads();
            // T1: block1 i=8..15
#pragma unroll
            for (int g = 0; g < 8; g++) { cf0[g] = sl0[8 + g] * sh40.x; cf1[g] = sl1[8 + g] * sh41.x; }
            tile16_attn(sW2, kb2 + 128, h2a, h2b, cf0, cf1, qs0, qs1, attn0, attn1);
            __syncthreads();
            copy_tile(sW2, g_W2kT + 8192, tid);
            __syncthreads();
            // T2: block2 i=0..7 (coef = C110*dot)
#pragma unroll
            for (int g = 0; g < 8; g++) { cf0[g] = sl0[16 + g]; cf1[g] = sl1[16 + g]; }
            tile16_attn(sW2, kb2 + 256, h2a, h2b, cf0, cf1, qs0, qs1, attn0, attn1);
        }
        __syncthreads();
        copy_tile(sW2, g_W2kT + 12288, tid);
        __syncthreads();
#pragma unroll
        for (int t = 0; t < 24; t++) { ov0[t] = 0.0f; ov1[t] = 0.0f; }
        tileT3(sW2, kb2 + 384, h2a, h2b, sl0, sl1,
               sh40.y, sh40.z, sh40.w, sh41.y, sh41.z, sh41.w, ov0, ov1);
        __syncthreads();
        copy_tile(sW2, g_W2kT + 16384, tid);
        __syncthreads();
        write_slabB(atom, dst0, sl0, sh40.y, sh40.z, sh40.w);
        write_slabB(atom, dst1, sl1, sh41.y, sh41.z, sh41.w);
        tileT4(sW2, kb2 + 512, h2a, h2b, sl0, sl1, sh40.x, sh41.x, ov0, ov1);

        // finish attention logits with vector q
        {
            float qv[24];
            const float4* q = (const float4*)(g_q + (size_t)src0 * 40 + 16);
#pragma unroll
            for (int i = 0; i < 6; i++) {
                float4 v = __ldg(q + i);
                qv[4 * i] = v.x; qv[4 * i + 1] = v.y; qv[4 * i + 2] = v.z; qv[4 * i + 3] = v.w;
            }
#pragma unroll
            for (int t = 0; t < 24; t++) attn0 = fmaf(ov0[t], qv[t], attn0);
            const float4* p = (const float4*)(g_q + (size_t)src1 * 40 + 16);
#pragma unroll
            for (int i = 0; i < 6; i++) {
                float4 v = __ldg(p + i);
                qv[4 * i] = v.x; qv[4 * i + 1] = v.y; qv[4 * i + 2] = v.z; qv[4 * i + 3] = v.w;
            }
#pragma unroll
            for (int t = 0; t < 24; t++) attn1 = fmaf(ov1[t], qv[t], attn1);
        }
        g_attn[e0] = attn0;
        g_attn[e1] = attn1;
        atomicMax(&g_m[src0], fkey(attn0));
        atomicMax(&g_m[src1], fkey(attn1));

        // ======================= V path =======================
        __syncthreads();
        copy_tile(sW2, g_W2vT, tid);
        mlp1_2(sW1v, sB1v, ef_g, e0, e1, h2a, h2b);
        write_slabA(atom, dst0, sl0, sh40.y, sh40.z, sh40.w);
        write_slabA(atom, dst1, sl1, sh41.y, sh41.z, sh41.w);
        {
            float os0[16], os1[16];
#pragma unroll
            for (int o = 0; o < 16; o++) { os0[o] = 0.0f; os1[o] = 0.0f; }
            float cf0[8], cf1[8];
            __syncthreads();
#pragma unroll
            for (int g = 0; g < 8; g++) { cf0[g] = sl0[g] * sh40.x; cf1[g] = sl1[g] * sh41.x; }
            tile16_os(sW2, vb2, h2a, h2b, cf0, cf1, os0, os1);
            __syncthreads();
            copy_tile(sW2, g_W2vT + 4096, tid);
            __syncthreads();
#pragma unroll
            for (int g = 0; g < 8; g++) { cf0[g] = sl0[8 + g] * sh40.x; cf1[g] = sl1[8 + g] * sh41.x; }
            tile16_os(sW2, vb2 + 128, h2a, h2b, cf0, cf1, os0, os1);
            __syncthreads();
            copy_tile(sW2, g_W2vT + 8192, tid);
            __syncthreads();
#pragma unroll
            for (int g = 0; g < 8; g++) { cf0[g] = sl0[16 + g]; cf1[g] = sl1[16 + g]; }
            tile16_os(sW2, vb2 + 256, h2a, h2b, cf0, cf1, os0, os1);
            // os final (blocks 1-2 only) -> store now, free registers
#pragma unroll
            for (int o = 0; o < 16; o++) {
                g_vT[(size_t)o * N_EDGES + e0] = os0[o];
                g_vT[(size_t)o * N_EDGES + e1] = os1[o];
            }
        }
        __syncthreads();
        copy_tile(sW2, g_W2vT + 12288, tid);
        __syncthreads();
#pragma unroll
        for (int t = 0; t < 24; t++) { ov0[t] = 0.0f; ov1[t] = 0.0f; }
        tileT3(sW2, vb2 + 384, h2a, h2b, sl0, sl1,
               sh40.y, sh40.z, sh40.w, sh41.y, sh41.z, sh41.w, ov0, ov1);
        __syncthreads();
        copy_tile(sW2, g_W2vT + 16384, tid);
        __syncthreads();
        write_slabB(atom, dst0, sl0, sh40.y, sh40.z, sh40.w);
        write_slabB(atom, dst1, sl1, sh41.y, sh41.z, sh41.w);
        tileT4(sW2, vb2 + 512, h2a, h2b, sl0, sl1, sh40.x, sh41.x, ov0, ov1);

#pragma unroll
        for (int t = 0; t < 24; t++) {
            g_vT[(size_t)(16 + t) * N_EDGES + e0] = ov0[t];
            g_vT[(size_t)(16 + t) * N_EDGES + e1] = ov1[t];
        }
    }
}

// ---------------- softmax accumulation ----------------
__global__ void k_soft(const int* __restrict__ eidx) {
    int e = blockIdx.x * 256 + threadIdx.x;
    if (e >= N_EDGES) return;
    int src = eidx[N_EDGES + e];
    float m = fdec(g_m[src]);
    float ex = expf(g_attn[e] - m);
    atomicAdd(&g_denom[src], ex);
#pragma unroll
    for (int f = 0; f < 40; f++) {
        atomicAdd(&g_numer[f * N_NODES + src], ex * g_vT[(size_t)f * N_EDGES + e]);
    }
}

// ---------------- pre-activation + batchnorm stats ----------------
__global__ void k_stats(const float* __restrict__ atom) {
    int f = blockIdx.y;
    int n = blockIdx.x * 256 + threadIdx.x;
    float pre = 0.0f;
    if (n < N_NODES) {
        float den = g_denom[n];
        float upd = (den > 0.0f) ? g_numer[f * N_NODES + n] / den : 0.0f;
        pre = atom[(size_t)n * 40 + f] + upd;
        g_pre[f * N_NODES + n] = pre;
    }
    float s = pre, ss = pre * pre;
    unsigned lane = threadIdx.x & 31, wid = threadIdx.x >> 5;
#pragma unroll
    for (int o = 16; o > 0; o >>= 1) {
        s += __shfl_down_sync(0xFFFFFFFFu, s, o);
        ss += __shfl_down_sync(0xFFFFFFFFu, ss, o);
    }
    __shared__ float rs[8], rss[8];
    if (lane == 0) { rs[wid] = s; rss[wid] = ss; }
    __syncthreads();
    if (threadIdx.x == 0) {
        float S = 0.0f, SS = 0.0f;
#pragma unroll
        for (int w = 0; w < 8; w++) { S += rs[w]; SS += rss[w]; }
        atomicAdd(&g_stats[f], S);
        atomicAdd(&g_stats[40 + f], SS);
    }
}

// ---------------- batchnorm finalize ----------------
__global__ void k_final(const float* __restrict__ bnws, const float* __restrict__ bnbs,
                        const float* __restrict__ bnwv, float* __restrict__ out) {
    int t = blockIdx.x * 256 + threadIdx.x;
    if (t >= 40 * N_NODES) return;
    int n = t / 40, f = t % 40;
    float pre = g_pre[f * N_NODES + n];
    float r;
    if (f < 16) {
        float mu = g_stats[f] * (1.0f / N_NODES);
        float var = g_stats[40 + f] * (1.0f / N_NODES) - mu * mu;
        r = (pre - mu) * rsqrtf(var + 1e-5f) * bnws[f] + bnbs[f];
    } else {
        int i = (f - 16) / 3;
        float nrm = (g_stats[40 + 16 + i * 3 + 0] + g_stats[40 + 16 + i * 3 + 1] +
                     g_stats[40 + 16 + i * 3 + 2]) * (1.0f / (3.0f * N_NODES));
        r = pre * rsqrtf(nrm + 1e-5f) * bnwv[i];
    }
    out[t] = r;
}

// ---------------- passthrough copy of edge_features ----------------
__global__ void k_copyef(const float* __restrict__ ef, float* __restrict__ out) {
    int t = blockIdx.x * 256 + threadIdx.x;
    if (t >= (N_EDGES * 32) / 4) return;
    ((float4*)out)[t] = ((const float4*)ef)[t];
}

// ---------------- launch ----------------
extern "C" void kernel_launch(void* const* d_in, const int* in_sizes, int n_in,
                              void* d_out, int out_size) {
    const float* atom = (const float*)d_in[0];
    const float* ef   = (const float*)d_in[1];
    const float* sh   = (const float*)d_in[2];
    const float* Wq_s = (const float*)d_in[3];
    const float* Wq_v = (const float*)d_in[4];
    const float* kw1  = (const float*)d_in[5];
    const float* kb1  = (const float*)d_in[6];
    const float* kw2  = (const float*)d_in[7];
    const float* kb2  = (const float*)d_in[8];
    const float* vw1  = (const float*)d_in[9];
    const float* vb1  = (const float*)d_in[10];
    const float* vw2  = (const float*)d_in[11];
    const float* vb2  = (const float*)d_in[12];
    const float* bnws = (const float*)d_in[13];
    const float* bnbs = (const float*)d_in[14];
    const float* bnwv = (const float*)d_in[15];
    const int*   eidx = (const int*)d_in[16];
    float* out = (float*)d_out;

    cudaFuncSetAttribute(k_edges, cudaFuncAttributeMaxDynamicSharedMemorySize, SMEM_BYTES);

    k_init<<<(40 * N_NODES + 255) / 256, 256>>>();
    k_transpose<<<(WN * 32 + 255) / 256, 256>>>(kw2, vw2);
    k_q<<<(40 * N_NODES + 255) / 256, 256>>>(atom, Wq_s, Wq_v);
    k_edges<<<EGRID, 128, SMEM_BYTES>>>(atom, ef, sh, eidx,
                                        kw1, kb1, kb2, vw1, vb1, vb2);
    k_soft<<<(N_EDGES + 255) / 256, 256>>>(eidx);
    dim3 gs((N_NODES + 255) / 256, 40);
    k_stats<<<gs, 256>>>(atom);
    k_final<<<(40 * N_NODES + 255) / 256, 256>>>(bnws, bnbs, bnwv, out);
    k_copyef<<<((N_EDGES * 32) / 4 + 255) / 256, 256>>>(ef, out + 40 * N_NODES);
}

// round 8
// speedup vs baseline: 1.2540x; 1.1477x over previous
#include <cuda_runtime.h>
#include <math.h>

#define N_NODES 10000
#define N_EDGES 160000
#define WN 640
#define C110 0.57735026918962576451f   /* 1/sqrt(3) */
#define C111 0.70710678118654752440f   /* 1/sqrt(2) */

#define CHUNK 256                      /* edges per chunk: 128 threads x 2 edges */
#define NCHUNK (N_EDGES / CHUNK)       /* 625, exact */
#define NITEMS (2 * NCHUNK)            /* 1250: (chunk, path) work items */
#define EGRID 444                      /* persistent CTAs (3 per SM) */

typedef unsigned long long u64;

// ---------------- device scratch ----------------
__device__ float g_W2kT[WN * 32];
__device__ float g_W2vT[WN * 32];
__device__ float g_q[N_NODES * 40];
__device__ float g_attn[N_EDGES];
__device__ float g_vT[40 * (size_t)N_EDGES];
__device__ int   g_m[N_NODES];
__device__ float g_denom[N_NODES];
__device__ float g_numer[40 * N_NODES];
__device__ float g_pre[40 * N_NODES];
__device__ float g_stats[80];
__device__ int   g_ticket;

// ---------------- packed f32x2 helpers ----------------
__device__ __forceinline__ u64 fma2(u64 a, u64 b, u64 c) {
    u64 d;
    asm("fma.rn.f32x2 %0, %1, %2, %3;" : "=l"(d) : "l"(a), "l"(b), "l"(c));
    return d;
}
__device__ __forceinline__ u64 pack2(float lo, float hi) {
    u64 r;
    asm("mov.b64 %0, {%1, %2};" : "=l"(r) : "f"(lo), "f"(hi));
    return r;
}
__device__ __forceinline__ float sum2(u64 v) {
    float a, b;
    asm("mov.b64 {%0, %1}, %2;" : "=f"(a), "=f"(b) : "l"(v));
    return a + b;
}

__device__ __forceinline__ int fkey(float f) {
    int b = __float_as_int(f);
    return (b >= 0) ? b : (int)(b ^ 0x7FFFFFFF);
}
__device__ __forceinline__ float fdec(int k) {
    return (k >= 0) ? __int_as_float(k) : __int_as_float((int)(k ^ 0x7FFFFFFF));
}

// ---------------- prep kernels ----------------
__global__ void k_init() {
    int i = blockIdx.x * 256 + threadIdx.x;
    if (i < 40 * N_NODES) g_numer[i] = 0.0f;
    if (i < N_NODES) { g_denom[i] = 0.0f; g_m[i] = (int)0x807FFFFFu; }
    if (i < 80) g_stats[i] = 0.0f;
    if (i == 0) g_ticket = 0;
}

__global__ void k_transpose(const float* __restrict__ kw2, const float* __restrict__ vw2) {
    int i = blockIdx.x * 256 + threadIdx.x;
    if (i < WN * 32) {
        int j = i / WN, c = i % WN;
        g_W2kT[c * 32 + j] = kw2[i];
        g_W2vT[c * 32 + j] = vw2[i];
    }
}

__global__ void k_q(const float* __restrict__ atom, const float* __restrict__ Wqs,
                    const float* __restrict__ Wqv) {
    int t = blockIdx.x * 256 + threadIdx.x;
    if (t >= 40 * N_NODES) return;
    int n = t / 40, f = t % 40;
    const float* a = atom + (size_t)n * 40;
    float acc = 0.0f;
    if (f < 16) {
#pragma unroll
        for (int i = 0; i < 16; i++) acc = fmaf(a[i], Wqs[i * 16 + f], acc);
    } else {
        int o = (f - 16) / 3, d = (f - 16) % 3;
#pragma unroll
        for (int i = 0; i < 8; i++) acc = fmaf(a[16 + i * 3 + d], Wqv[i * 8 + o], acc);
    }
    g_q[t] = acc;
}

// ---------------- shared 2-edge dot over one 32-wide column ----------------
__device__ __forceinline__ void dot2e(const float* __restrict__ w,
                                      const u64 (&ha)[16], const u64 (&hb)[16],
                                      float& r0, float& r1) {
    const ulonglong2* wp = (const ulonglong2*)w;
    u64 a0 = 0, b0 = 0, a1 = 0, b1 = 0;
#pragma unroll
    for (int j = 0; j < 4; j++) {
        ulonglong2 w1 = wp[2 * j], w2 = wp[2 * j + 1];
        a0 = fma2(ha[4 * j + 0], w1.x, a0);
        b0 = fma2(ha[4 * j + 1], w1.y, b0);
        a0 = fma2(ha[4 * j + 2], w2.x, a0);
        b0 = fma2(ha[4 * j + 3], w2.y, b0);
        a1 = fma2(hb[4 * j + 0], w1.x, a1);
        b1 = fma2(hb[4 * j + 1], w1.y, b1);
        a1 = fma2(hb[4 * j + 2], w2.x, a1);
        b1 = fma2(hb[4 * j + 3], w2.y, b1);
    }
    r0 = sum2(a0) + sum2(b0);
    r1 = sum2(a1) + sum2(b1);
}

// ---------------- MLP layer-1 for two edges ----------------
__device__ __forceinline__ void load_ef2(const float* __restrict__ ef_g, int e, u64 (&ef2)[16]) {
    const float4* p = (const float4*)(ef_g + (size_t)e * 32);
#pragma unroll
    for (int i = 0; i < 8; i++) {
        float4 v = __ldg(p + i);
        ef2[2 * i + 0] = pack2(v.x, v.y);
        ef2[2 * i + 1] = pack2(v.z, v.w);
    }
}

__device__ __forceinline__ void mlp1_2(const float* __restrict__ sW1T,
                                       const float* __restrict__ sB1,
                                       const float* __restrict__ ef_g, int e0, int e1,
                                       u64 (&h2a)[16], u64 (&h2b)[16]) {
    u64 efa[16], efb[16];
    load_ef2(ef_g, e0, efa);
    load_ef2(ef_g, e1, efb);
#pragma unroll 1
    for (int c = 0; c < 16; c++) {
        float r0a, r0b, r1a, r1b;
        dot2e(sW1T + (2 * c) * 32, efa, efb, r0a, r0b);
        dot2e(sW1T + (2 * c + 1) * 32, efa, efb, r1a, r1b);
        float b0 = sB1[2 * c], b1 = sB1[2 * c + 1];
        h2a[c] = pack2(fmaxf(r0a + b0, 0.0f), fmaxf(r1a + b1, 0.0f));
        h2b[c] = pack2(fmaxf(r0b + b0, 0.0f), fmaxf(r1b + b1, 0.0f));
    }
}

// ---------------- coefficient slab writers ----------------
// slabA per edge (24 floats): [0..15]=x_s, [16..23]=C110*dot(x_v, sh_v)
__device__ __forceinline__ void write_slabA(const float* __restrict__ atom, int node,
                                            float* __restrict__ sl,
                                            float s0, float s1, float s2) {
    const float4* p = (const float4*)(atom + (size_t)node * 40);
#pragma unroll
    for (int i = 0; i < 4; i++) {
        float4 v = __ldg(p + i);
        sl[4 * i + 0] = v.x; sl[4 * i + 1] = v.y; sl[4 * i + 2] = v.z; sl[4 * i + 3] = v.w;
    }
    float xv[24];
#pragma unroll
    for (int i = 0; i < 6; i++) {
        float4 v = __ldg(p + 4 + i);
        xv[4 * i + 0] = v.x; xv[4 * i + 1] = v.y; xv[4 * i + 2] = v.z; xv[4 * i + 3] = v.w;
    }
#pragma unroll
    for (int i = 0; i < 8; i++)
        sl[16 + i] = C110 * (xv[3 * i] * s0 + xv[3 * i + 1] * s1 + xv[3 * i + 2] * s2);
}

// slabB per edge (48 floats): [0..23]=x_v, [24..47]=C111*cross(x_v, sh_v)
__device__ __forceinline__ void write_slabB(const float* __restrict__ atom, int node,
                                            float* __restrict__ sl,
                                            float s0, float s1, float s2) {
    const float4* p = (const float4*)(atom + (size_t)node * 40);
    float xv[24];
#pragma unroll
    for (int i = 0; i < 6; i++) {
        float4 v = __ldg(p + 4 + i);
        xv[4 * i + 0] = v.x; xv[4 * i + 1] = v.y; xv[4 * i + 2] = v.z; xv[4 * i + 3] = v.w;
    }
#pragma unroll
    for (int i = 0; i < 8; i++) {
        float a0 = xv[3 * i], a1 = xv[3 * i + 1], a2 = xv[3 * i + 2];
        sl[i * 3 + 0] = a0; sl[i * 3 + 1] = a1; sl[i * 3 + 2] = a2;
        sl[24 + i * 3 + 0] = C111 * (a1 * s2 - a2 * s1);
        sl[24 + i * 3 + 1] = C111 * (a2 * s0 - a0 * s2);
        sl[24 + i * 3 + 2] = C111 * (a0 * s1 - a1 * s0);
    }
}

// ---------------- per-tile GEMM+fold workers (128 cols/tile) ----------------
__device__ __forceinline__ void tile16_attn(const float* __restrict__ sW2,
                                            const float* __restrict__ b2g,
                                            const u64 (&h0)[16], const u64 (&h1)[16],
                                            const float (&cf0)[8], const float (&cf1)[8],
                                            const float (&qs0)[16], const float (&qs1)[16],
                                            float& attn0, float& attn1) {
#pragma unroll 1
    for (int g = 0; g < 8; g++) {
        const float* wb = sW2 + g * 16 * 32;
        float c0 = cf0[g], c1 = cf1[g];
#pragma unroll
        for (int o = 0; o < 16; o++) {
            float a0, a1;
            dot2e(wb + o * 32, h0, h1, a0, a1);
            float b = __ldg(b2g + g * 16 + o);
            attn0 = fmaf(c0 * (a0 + b), qs0[o], attn0);
            attn1 = fmaf(c1 * (a1 + b), qs1[o], attn1);
        }
    }
}

__device__ __forceinline__ void tile16_os(const float* __restrict__ sW2,
                                          const float* __restrict__ b2g,
                                          const u64 (&h0)[16], const u64 (&h1)[16],
                                          const float (&cf0)[8], const float (&cf1)[8],
                                          float (&os0)[16], float (&os1)[16]) {
#pragma unroll 1
    for (int g = 0; g < 8; g++) {
        const float* wb = sW2 + g * 16 * 32;
        float c0 = cf0[g], c1 = cf1[g];
#pragma unroll
        for (int o = 0; o < 16; o++) {
            float a0, a1;
            dot2e(wb + o * 32, h0, h1, a0, a1);
            float b = __ldg(b2g + g * 16 + o);
            os0[o] = fmaf(c0, a0 + b, os0[o]);
            os1[o] = fmaf(c1, a1 + b, os1[o]);
        }
    }
}

// Tile 3 (block 3, cols 384..511)
__device__ __forceinline__ void tileT3(const float* __restrict__ sW2,
                                       const float* __restrict__ b2g,
                                       const u64 (&h0)[16], const u64 (&h1)[16],
                                       const float* __restrict__ sl0, const float* __restrict__ sl1,
                                       float s00, float s01, float s02,
                                       float s10, float s11, float s12,
                                       float (&ov0)[24], float (&ov1)[24]) {
#pragma unroll 1
    for (int i = 0; i < 16; i++) {
        float ci0 = sl0[i], ci1 = sl1[i];
        const float* wb = sW2 + i * 8 * 32;
#pragma unroll
        for (int o = 0; o < 8; o++) {
            float a0, a1;
            dot2e(wb + o * 32, h0, h1, a0, a1);
            float b = __ldg(b2g + i * 8 + o);
            float t0 = ci0 * (a0 + b), t1 = ci1 * (a1 + b);
            ov0[o * 3 + 0] = fmaf(t0, s00, ov0[o * 3 + 0]);
            ov0[o * 3 + 1] = fmaf(t0, s01, ov0[o * 3 + 1]);
            ov0[o * 3 + 2] = fmaf(t0, s02, ov0[o * 3 + 2]);
            ov1[o * 3 + 0] = fmaf(t1, s10, ov1[o * 3 + 0]);
            ov1[o * 3 + 1] = fmaf(t1, s11, ov1[o * 3 + 1]);
            ov1[o * 3 + 2] = fmaf(t1, s12, ov1[o * 3 + 2]);
        }
    }
}

// Tile 4 (blocks 4+5, cols 512..639)
__device__ __forceinline__ void tileT4(const float* __restrict__ sW2,
                                       const float* __restrict__ b2g,
                                       const u64 (&h0)[16], const u64 (&h1)[16],
                                       const float* __restrict__ sl0, const float* __restrict__ sl1,
                                       float shs0, float shs1,
                                       float (&ov0)[24], float (&ov1)[24]) {
#pragma unroll 1
    for (int i = 0; i < 8; i++) {
        const float* wb = sW2 + i * 8 * 32;
        float x00 = sl0[i * 3 + 0], x01 = sl0[i * 3 + 1], x02 = sl0[i * 3 + 2];
        float x10 = sl1[i * 3 + 0], x11 = sl1[i * 3 + 1], x12 = sl1[i * 3 + 2];
#pragma unroll
        for (int o = 0; o < 8; o++) {
            float a0, a1;
            dot2e(wb + o * 32, h0, h1, a0, a1);
            float b = __ldg(b2g + i * 8 + o);
            float t0 = shs0 * (a0 + b), t1 = shs1 * (a1 + b);
            ov0[o * 3 + 0] = fmaf(t0, x00, ov0[o * 3 + 0]);
            ov0[o * 3 + 1] = fmaf(t0, x01, ov0[o * 3 + 1]);
            ov0[o * 3 + 2] = fmaf(t0, x02, ov0[o * 3 + 2]);
            ov1[o * 3 + 0] = fmaf(t1, x10, ov1[o * 3 + 0]);
            ov1[o * 3 + 1] = fmaf(t1, x11, ov1[o * 3 + 1]);
            ov1[o * 3 + 2] = fmaf(t1, x12, ov1[o * 3 + 2]);
        }
    }
#pragma unroll 1
    for (int i = 0; i < 8; i++) {
        const float* wb = sW2 + (64 + i * 8) * 32;
        float c00 = sl0[24 + i * 3 + 0], c01 = sl0[24 + i * 3 + 1], c02 = sl0[24 + i * 3 + 2];
        float c10 = sl1[24 + i * 3 + 0], c11 = sl1[24 + i * 3 + 1], c12 = sl1[24 + i * 3 + 2];
#pragma unroll
        for (int o = 0; o < 8; o++) {
            float a0, a1;
            dot2e(wb + o * 32, h0, h1, a0, a1);
            float b = __ldg(b2g + 64 + i * 8 + o);
            a0 += b; a1 += b;
            ov0[o * 3 + 0] = fmaf(a0, c00, ov0[o * 3 + 0]);
            ov0[o * 3 + 1] = fmaf(a0, c01, ov0[o * 3 + 1]);
            ov0[o * 3 + 2] = fmaf(a0, c02, ov0[o * 3 + 2]);
            ov1[o * 3 + 0] = fmaf(a1, c10, ov1[o * 3 + 0]);
            ov1[o * 3 + 1] = fmaf(a1, c11, ov1[o * 3 + 1]);
            ov1[o * 3 + 2] = fmaf(a1, c12, ov1[o * 3 + 2]);
        }
    }
}

// ---------------- smem layout (floats) ----------------
#define SM_W2    0                    /* 128-col tile: 4096 floats (16KB) */
#define SM_W1K   4096
#define SM_W1V   (SM_W1K + 1024)
#define SM_B1K   (SM_W1V + 1024)
#define SM_B1V   (SM_B1K + 32)
#define SM_SLAB  (SM_B1V + 32)        /* 128 threads x 97 floats */
#define SM_TOTAL (SM_SLAB + 128 * 97)
#define SMEM_BYTES (SM_TOTAL * 4)     /* 74496 bytes -> 3 CTAs/SM */

__device__ __forceinline__ void copy_tile(float* __restrict__ dst, const float* __restrict__ src,
                                          int tid) {
    const float4* s = (const float4*)src;
    float4* d = (float4*)dst;
#pragma unroll
    for (int k = 0; k < 8; k++) d[tid + 128 * k] = s[tid + 128 * k];
}

__global__ __launch_bounds__(128, 3) void k_edges(
    const float* __restrict__ atom, const float* __restrict__ ef_g,
    const float* __restrict__ sh_g, const int* __restrict__ eidx,
    const float* __restrict__ kw1, const float* __restrict__ kb1, const float* __restrict__ kb2,
    const float* __restrict__ vw1, const float* __restrict__ vb1, const float* __restrict__ vb2) {
    extern __shared__ float sm[];
    float* sW2  = sm + SM_W2;
    float* sW1k = sm + SM_W1K;
    float* sW1v = sm + SM_W1V;
    float* sB1k = sm + SM_B1K;
    float* sB1v = sm + SM_B1V;
    int tid = threadIdx.x;
    float* sl0 = sm + SM_SLAB + tid * 97;
    float* sl1 = sl0 + 48;
    __shared__ int sTicket;

    // one-time staging of W1 (transposed) + layer-1 biases
    for (int i = tid; i < 1024; i += 128) {
        sW1k[(i % 32) * 32 + (i / 32)] = kw1[i];
        sW1v[(i % 32) * 32 + (i / 32)] = vw1[i];
    }
    if (tid < 32) { sB1k[tid] = kb1[tid]; sB1v[tid] = vb1[tid]; }

    for (;;) {
        __syncthreads();  // prior item's last tile use done; staging visible first pass
        if (tid == 0) sTicket = atomicAdd(&g_ticket, 1);
        __syncthreads();
        int item = sTicket;
        if (item >= NITEMS) break;
        int chunk = item >> 1;
        int path = item & 1;  // 0 = K, 1 = V

        int e0 = chunk * CHUNK + tid;
        int e1 = e0 + 128;

        int dst0 = __ldg(eidx + e0), dst1 = __ldg(eidx + e1);
        float4 sh40 = __ldg(((const float4*)sh_g) + e0);
        float4 sh41 = __ldg(((const float4*)sh_g) + e1);

        const float* W2g = path ? g_W2vT : g_W2kT;
        const float* b2  = path ? vb2 : kb2;
        const float* sW1 = path ? sW1v : sW1k;
        const float* sB1 = path ? sB1v : sB1k;

        u64 h2a[16], h2b[16];
        float ov0[24], ov1[24];
        float cf0[8], cf1[8];

        copy_tile(sW2, W2g, tid);
        mlp1_2(sW1, sB1, ef_g, e0, e1, h2a, h2b);
        write_slabA(atom, dst0, sl0, sh40.y, sh40.z, sh40.w);
        write_slabA(atom, dst1, sl1, sh41.y, sh41.z, sh41.w);

        if (path == 0) {
            // ======================= K item: attention logits =======================
            int src0 = __ldg(eidx + N_EDGES + e0), src1 = __ldg(eidx + N_EDGES + e1);
            float attn0 = 0.0f, attn1 = 0.0f;
            {
                float qs0[16], qs1[16];
                {
                    const float4* q = (const float4*)(g_q + (size_t)src0 * 40);
#pragma unroll
                    for (int i = 0; i < 4; i++) {
                        float4 v = __ldg(q + i);
                        qs0[4 * i] = v.x; qs0[4 * i + 1] = v.y; qs0[4 * i + 2] = v.z; qs0[4 * i + 3] = v.w;
                    }
                    const float4* p = (const float4*)(g_q + (size_t)src1 * 40);
#pragma unroll
                    for (int i = 0; i < 4; i++) {
                        float4 v = __ldg(p + i);
                        qs1[4 * i] = v.x; qs1[4 * i + 1] = v.y; qs1[4 * i + 2] = v.z; qs1[4 * i + 3] = v.w;
                    }
                }
                __syncthreads();  // tile0 ready
#pragma unroll
                for (int g = 0; g < 8; g++) { cf0[g] = sl0[g] * sh40.x; cf1[g] = sl1[g] * sh41.x; }
                tile16_attn(sW2, b2, h2a, h2b, cf0, cf1, qs0, qs1, attn0, attn1);
                __syncthreads();
                copy_tile(sW2, W2g + 4096, tid);
                __syncthreads();
#pragma unroll
                for (int g = 0; g < 8; g++) { cf0[g] = sl0[8 + g] * sh40.x; cf1[g] = sl1[8 + g] * sh41.x; }
                tile16_attn(sW2, b2 + 128, h2a, h2b, cf0, cf1, qs0, qs1, attn0, attn1);
                __syncthreads();
                copy_tile(sW2, W2g + 8192, tid);
                __syncthreads();
#pragma unroll
                for (int g = 0; g < 8; g++) { cf0[g] = sl0[16 + g]; cf1[g] = sl1[16 + g]; }
                tile16_attn(sW2, b2 + 256, h2a, h2b, cf0, cf1, qs0, qs1, attn0, attn1);
            }
            __syncthreads();
            copy_tile(sW2, W2g + 12288, tid);
            __syncthreads();
#pragma unroll
            for (int t = 0; t < 24; t++) { ov0[t] = 0.0f; ov1[t] = 0.0f; }
            tileT3(sW2, b2 + 384, h2a, h2b, sl0, sl1,
                   sh40.y, sh40.z, sh40.w, sh41.y, sh41.z, sh41.w, ov0, ov1);
            __syncthreads();
            copy_tile(sW2, W2g + 16384, tid);
            __syncthreads();
            write_slabB(atom, dst0, sl0, sh40.y, sh40.z, sh40.w);
            write_slabB(atom, dst1, sl1, sh41.y, sh41.z, sh41.w);
            tileT4(sW2, b2 + 512, h2a, h2b, sl0, sl1, sh40.x, sh41.x, ov0, ov1);

            {
                float qv[24];
                const float4* q = (const float4*)(g_q + (size_t)src0 * 40 + 16);
#pragma unroll
                for (int i = 0; i < 6; i++) {
                    float4 v = __ldg(q + i);
                    qv[4 * i] = v.x; qv[4 * i + 1] = v.y; qv[4 * i + 2] = v.z; qv[4 * i + 3] = v.w;
                }
#pragma unroll
                for (int t = 0; t < 24; t++) attn0 = fmaf(ov0[t], qv[t], attn0);
                const float4* p = (const float4*)(g_q + (size_t)src1 * 40 + 16);
#pragma unroll
                for (int i = 0; i < 6; i++) {
                    float4 v = __ldg(p + i);
                    qv[4 * i] = v.x; qv[4 * i + 1] = v.y; qv[4 * i + 2] = v.z; qv[4 * i + 3] = v.w;
                }
#pragma unroll
                for (int t = 0; t < 24; t++) attn1 = fmaf(ov1[t], qv[t], attn1);
            }
            g_attn[e0] = attn0;
            g_attn[e1] = attn1;
            atomicMax(&g_m[src0], fkey(attn0));
            atomicMax(&g_m[src1], fkey(attn1));
        } else {
            // ======================= V item: value irreps =======================
            {
                float os0[16], os1[16];
#pragma unroll
                for (int o = 0; o < 16; o++) { os0[o] = 0.0f; os1[o] = 0.0f; }
                __syncthreads();  // tile0 ready
#pragma unroll
                for (int g = 0; g < 8; g++) { cf0[g] = sl0[g] * sh40.x; cf1[g] = sl1[g] * sh41.x; }
                tile16_os(sW2, b2, h2a, h2b, cf0, cf1, os0, os1);
                __syncthreads();
                copy_tile(sW2, W2g + 4096, tid);
                __syncthreads();
#pragma unroll
                for (int g = 0; g < 8; g++) { cf0[g] = sl0[8 + g] * sh40.x; cf1[g] = sl1[8 + g] * sh41.x; }
                tile16_os(sW2, b2 + 128, h2a, h2b, cf0, cf1, os0, os1);
                __syncthreads();
                copy_tile(sW2, W2g + 8192, tid);
                __syncthreads();
#pragma unroll
                for (int g = 0; g < 8; g++) { cf0[g] = sl0[16 + g]; cf1[g] = sl1[16 + g]; }
                tile16_os(sW2, b2 + 256, h2a, h2b, cf0, cf1, os0, os1);
                // scalar part final after blocks 1-2 -> store, free registers
#pragma unroll
                for (int o = 0; o < 16; o++) {
                    g_vT[(size_t)o * N_EDGES + e0] = os0[o];
                    g_vT[(size_t)o * N_EDGES + e1] = os1[o];
                }
            }
            __syncthreads();
            copy_tile(sW2, W2g + 12288, tid);
            __syncthreads();
#pragma unroll
            for (int t = 0; t < 24; t++) { ov0[t] = 0.0f; ov1[t] = 0.0f; }
            tileT3(sW2, b2 + 384, h2a, h2b, sl0, sl1,
                   sh40.y, sh40.z, sh40.w, sh41.y, sh41.z, sh41.w, ov0, ov1);
            __syncthreads();
            copy_tile(sW2, W2g + 16384, tid);
            __syncthreads();
            write_slabB(atom, dst0, sl0, sh40.y, sh40.z, sh40.w);
            write_slabB(atom, dst1, sl1, sh41.y, sh41.z, sh41.w);
            tileT4(sW2, b2 + 512, h2a, h2b, sl0, sl1, sh40.x, sh41.x, ov0, ov1);

#pragma unroll
            for (int t = 0; t < 24; t++) {
                g_vT[(size_t)(16 + t) * N_EDGES + e0] = ov0[t];
                g_vT[(size_t)(16 + t) * N_EDGES + e1] = ov1[t];
            }
        }
    }
}

// ---------------- softmax accumulation ----------------
__global__ void k_soft(const int* __restrict__ eidx) {
    int e = blockIdx.x * 256 + threadIdx.x;
    if (e >= N_EDGES) return;
    int src = eidx[N_EDGES + e];
    float m = fdec(g_m[src]);
    float ex = expf(g_attn[e] - m);
    atomicAdd(&g_denom[src], ex);
#pragma unroll
    for (int f = 0; f < 40; f++) {
        atomicAdd(&g_numer[f * N_NODES + src], ex * g_vT[(size_t)f * N_EDGES + e]);
    }
}

// ---------------- pre-activation + batchnorm stats ----------------
__global__ void k_stats(const float* __restrict__ atom) {
    int f = blockIdx.y;
    int n = blockIdx.x * 256 + threadIdx.x;
    float pre = 0.0f;
    if (n < N_NODES) {
        float den = g_denom[n];
        float upd = (den > 0.0f) ? g_numer[f * N_NODES + n] / den : 0.0f;
        pre = atom[(size_t)n * 40 + f] + upd;
        g_pre[f * N_NODES + n] = pre;
    }
    float s = pre, ss = pre * pre;
    unsigned lane = threadIdx.x & 31, wid = threadIdx.x >> 5;
#pragma unroll
    for (int o = 16; o > 0; o >>= 1) {
        s += __shfl_down_sync(0xFFFFFFFFu, s, o);
        ss += __shfl_down_sync(0xFFFFFFFFu, ss, o);
    }
    __shared__ float rs[8], rss[8];
    if (lane == 0) { rs[wid] = s; rss[wid] = ss; }
    __syncthreads();
    if (threadIdx.x == 0) {
        float S = 0.0f, SS = 0.0f;
#pragma unroll
        for (int w = 0; w < 8; w++) { S += rs[w]; SS += rss[w]; }
        atomicAdd(&g_stats[f], S);
        atomicAdd(&g_stats[40 + f], SS);
    }
}

// ---------------- batchnorm finalize ----------------
__global__ void k_final(const float* __restrict__ bnws, const float* __restrict__ bnbs,
                        const float* __restrict__ bnwv, float* __restrict__ out) {
    int t = blockIdx.x * 256 + threadIdx.x;
    if (t >= 40 * N_NODES) return;
    int n = t / 40, f = t % 40;
    float pre = g_pre[f * N_NODES + n];
    float r;
    if (f < 16) {
        float mu = g_stats[f] * (1.0f / N_NODES);
        float var = g_stats[40 + f] * (1.0f / N_NODES) - mu * mu;
        r = (pre - mu) * rsqrtf(var + 1e-5f) * bnws[f] + bnbs[f];
    } else {
        int i = (f - 16) / 3;
        float nrm = (g_stats[40 + 16 + i * 3 + 0] + g_stats[40 + 16 + i * 3 + 1] +
                     g_stats[40 + 16 + i * 3 + 2]) * (1.0f / (3.0f * N_NODES));
        r = pre * rsqrtf(nrm + 1e-5f) * bnwv[i];
    }
    out[t] = r;
}

// ---------------- passthrough copy of edge_features ----------------
__global__ void k_copyef(const float* __restrict__ ef, float* __restrict__ out) {
    int t = blockIdx.x * 256 + threadIdx.x;
    if (t >= (N_EDGES * 32) / 4) return;
    ((float4*)out)[t] = ((const float4*)ef)[t];
}

// ---------------- launch ----------------
extern "C" void kernel_launch(void* const* d_in, const int* in_sizes, int n_in,
                              void* d_out, int out_size) {
    const float* atom = (const float*)d_in[0];
    const float* ef   = (const float*)d_in[1];
    const float* sh   = (const float*)d_in[2];
    const float* Wq_s = (const float*)d_in[3];
    const float* Wq_v = (const float*)d_in[4];
    const float* kw1  = (const float*)d_in[5];
    const float* kb1  = (const float*)d_in[6];
    const float* kw2  = (const float*)d_in[7];
    const float* kb2  = (const float*)d_in[8];
    const float* vw1  = (const float*)d_in[9];
    const float* vb1  = (const float*)d_in[10];
    const float* vw2  = (const float*)d_in[11];
    const float* vb2  = (const float*)d_in[12];
    const float* bnws = (const float*)d_in[13];
    const float* bnbs = (const float*)d_in[14];
    const float* bnwv = (const float*)d_in[15];
    const int*   eidx = (const int*)d_in[16];
    float* out = (float*)d_out;

    cudaFuncSetAttribute(k_edges, cudaFuncAttributeMaxDynamicSharedMemorySize, SMEM_BYTES);

    k_init<<<(40 * N_NODES + 255) / 256, 256>>>();
    k_transpose<<<(WN * 32 + 255) / 256, 256>>>(kw2, vw2);
    k_q<<<(40 * N_NODES + 255) / 256, 256>>>(atom, Wq_s, Wq_v);
    k_edges<<<EGRID, 128, SMEM_BYTES>>>(atom, ef, sh, eidx,
                                        kw1, kb1, kb2, vw1, vb1, vb2);
    k_soft<<<(N_EDGES + 255) / 256, 256>>>(eidx);
    dim3 gs((N_NODES + 255) / 256, 40);
    k_stats<<<gs, 256>>>(atom);
    k_final<<<(40 * N_NODES + 255) / 256, 256>>>(bnws, bnbs, bnwv, out);
    k_copyef<<<((N_EDGES * 32) / 4 + 255) / 256, 256>>>(ef, out + 40 * N_NODES);
}

// round 15
// speedup vs baseline: 2.0571x; 1.6405x over previous
#include <cuda_runtime.h>
#include <cuda_bf16.h>
#include <math.h>

#define N_NODES 10000
#define N_EDGES 160000
#define WN 640
#define C110 0.57735026918962576451f   /* 1/sqrt(3) */
#define C111 0.70710678118654752440f   /* 1/sqrt(2) */

#define CHUNK 128                      /* edges per chunk */
#define NCHUNK (N_EDGES / CHUNK)       /* 1250 */
#define NITEMS (2 * NCHUNK)            /* 2500 (chunk, path) items */
#define EGRID 296                      /* persistent CTAs, 2/SM */

typedef unsigned long long u64;
typedef unsigned int u32;
typedef unsigned short u16;

// ---------------- device scratch ----------------
__device__ __align__(16) u64 g_Wfrag[2 * 80 * 7 * 32];  /* fragment-ordered W images */
__device__ float g_q[N_NODES * 40];
__device__ float g_attn[N_EDGES];
__device__ float g_vT[40 * (size_t)N_EDGES];
__device__ int   g_m[N_NODES];
__device__ float g_denom[N_NODES];
__device__ float g_numer[40 * N_NODES];
__device__ float g_pre[40 * N_NODES];
__device__ float g_stats[80];
__device__ int   g_ticket;

// ---------------- small helpers ----------------
__device__ __forceinline__ u64 fma2(u64 a, u64 b, u64 c) {
    u64 d;
    asm("fma.rn.f32x2 %0, %1, %2, %3;" : "=l"(d) : "l"(a), "l"(b), "l"(c));
    return d;
}
__device__ __forceinline__ u64 pack2(float lo, float hi) {
    u64 r;
    asm("mov.b64 %0, {%1, %2};" : "=l"(r) : "f"(lo), "f"(hi));
    return r;
}
__device__ __forceinline__ float sum2(u64 v) {
    float a, b;
    asm("mov.b64 {%0, %1}, %2;" : "=f"(a), "=f"(b) : "l"(v));
    return a + b;
}
__device__ __forceinline__ int fkey(float f) {
    int b = __float_as_int(f);
    return (b >= 0) ? b : (int)(b ^ 0x7FFFFFFF);
}
__device__ __forceinline__ float fdec(int k) {
    return (k >= 0) ? __int_as_float(k) : __int_as_float((int)(k ^ 0x7FFFFFFF));
}
__device__ __forceinline__ u16 f2bf(float x) {
    __nv_bfloat16 h = __float2bfloat16(x);
    return *reinterpret_cast<u16*>(&h);
}
__device__ __forceinline__ float bf2f(u16 b) {
    __nv_bfloat16 h = *reinterpret_cast<__nv_bfloat16*>(&b);
    return __bfloat162float(h);
}
__device__ __forceinline__ u32 smem_u32(const void* p) {
    u32 a;
    asm("{ .reg .u64 t; cvta.to.shared.u64 t, %1; cvt.u32.u64 %0, t; }" : "=r"(a) : "l"(p));
    return a;
}

#define MMA_BF16(d0, d1, d2, d3, a0, a1, a2, a3, b0, b1) \
    asm volatile("mma.sync.aligned.m16n8k16.row.col.f32.bf16.bf16.f32 " \
                 "{%0,%1,%2,%3}, {%4,%5,%6,%7}, {%8,%9}, {%0,%1,%2,%3};" \
                 : "+f"(d0), "+f"(d1), "+f"(d2), "+f"(d3) \
                 : "r"(a0), "r"(a1), "r"(a2), "r"(a3), "r"(b0), "r"(b1))

#define LDMATRIX_X4(r0, r1, r2, r3, addr) \
    asm volatile("ldmatrix.sync.aligned.m8n8.x4.shared.b16 {%0,%1,%2,%3}, [%4];" \
                 : "=r"(r0), "=r"(r1), "=r"(r2), "=r"(r3) : "r"(addr))

// ---------------- prep kernels ----------------
__global__ void k_init() {
    int i = blockIdx.x * 256 + threadIdx.x;
    if (i < 40 * N_NODES) g_numer[i] = 0.0f;
    if (i < N_NODES) { g_denom[i] = 0.0f; g_m[i] = (int)0x807FFFFFu; }
    if (i < 80) g_stats[i] = 0.0f;
    if (i == 0) g_ticket = 0;
}

__global__ void k_q(const float* __restrict__ atom, const float* __restrict__ Wqs,
                    const float* __restrict__ Wqv) {
    int t = blockIdx.x * 256 + threadIdx.x;
    if (t >= 40 * N_NODES) return;
    int n = t / 40, f = t % 40;
    const float* a = atom + (size_t)n * 40;
    float acc = 0.0f;
    if (f < 16) {
#pragma unroll
        for (int i = 0; i < 16; i++) acc = fmaf(a[i], Wqs[i * 16 + f], acc);
    } else {
        int o = (f - 16) / 3, d = (f - 16) % 3;
#pragma unroll
        for (int i = 0; i < 8; i++) acc = fmaf(a[16 + i * 3 + d], Wqv[i * 8 + o], acc);
    }
    g_q[t] = acc;
}

// Build fragment-ordered W image.
// K layout (112): kpos<32: Whi[k][n]; 32..63: Whi[k-32]; 64..95: Wlo[k-64];
// 96: bhi; 97: blo; 98..111: 0.  (A rows: hhi | hlo | hhi | 1,1 | 0)
__global__ void k_wstk(const float* __restrict__ kw2, const float* __restrict__ kb2,
                       const float* __restrict__ vw2, const float* __restrict__ vb2) {
    int idx = blockIdx.x * 256 + threadIdx.x;
    if (idx >= 2 * 80 * 7 * 32) return;
    int p = idx / (80 * 7 * 32);
    int rem = idx % (80 * 7 * 32);
    int ng = rem / (7 * 32);
    int rem2 = rem % (7 * 32);
    int s = rem2 / 32;
    int lane = rem2 % 32;
    int n = ng * 8 + (lane >> 2);
    int m = lane & 3;
    const float* w = p ? vw2 : kw2;
    const float* b = p ? vb2 : kb2;
    u16 v[4];
#pragma unroll
    for (int t = 0; t < 4; t++) {
        int kl = 2 * m + (t & 1) + (t >> 1) * 8;
        int kpos = s * 16 + kl;
        u16 bits = 0;
        if (kpos < 32) bits = f2bf(w[kpos * WN + n]);
        else if (kpos < 64) bits = f2bf(w[(kpos - 32) * WN + n]);
        else if (kpos < 96) {
            float x = w[(kpos - 64) * WN + n];
            bits = f2bf(x - bf2f(f2bf(x)));
        } else if (kpos == 96) bits = f2bf(b[n]);
        else if (kpos == 97) {
            float x = b[n];
            bits = f2bf(x - bf2f(f2bf(x)));
        }
        v[t] = bits;
    }
    u64 pk = (u64)((u32)v[0] | ((u32)v[1] << 16)) |
             ((u64)((u32)v[2] | ((u32)v[3] << 16)) << 32);
    g_Wfrag[idx] = pk;
}

// smem float offsets
#define SM_A    0                 /* 128 x 120 bf16 = 7680 floats */
#define SM_W1K  7680
#define SM_W1V  (SM_W1K + 1024)
#define SM_B1K  (SM_W1V + 1024)
#define SM_B1V  (SM_B1K + 32)
#define SM_SLAB (SM_B1V + 32)     /* 128 x 77 floats */
#define SM_TOTAL (SM_SLAB + 128 * 77)
#define SMEM_BYTES (SM_TOTAL * 4)

__global__ __launch_bounds__(128, 2) void k_edges(
    const float* __restrict__ atom, const float* __restrict__ ef_g,
    const float* __restrict__ sh_g, const int* __restrict__ eidx,
    const float* __restrict__ kw1, const float* __restrict__ kb1,
    const float* __restrict__ vw1, const float* __restrict__ vb1) {
    extern __shared__ float sm[];
    __shared__ int sTicket;
    int tid = threadIdx.x;
    int warp = tid >> 5, lane = tid & 31;
    int q = lane >> 2, m = lane & 3;
    u32 sA = smem_u32(sm);

    // one-time staging: W1 (transposed) + b1
    for (int i = tid; i < 1024; i += 128) {
        sm[SM_W1K + (i % 32) * 32 + (i / 32)] = kw1[i];
        sm[SM_W1V + (i % 32) * 32 + (i / 32)] = vw1[i];
    }
    if (tid < 32) { sm[SM_B1K + tid] = kb1[tid]; sm[SM_B1V + tid] = vb1[tid]; }

    for (;;) {
        __syncthreads();
        if (tid == 0) sTicket = atomicAdd(&g_ticket, 1);
        __syncthreads();
        int item = sTicket;
        if (item >= NITEMS) break;
        int chunk = item >> 1, path = item & 1;
        int e = chunk * CHUNK + tid;

        // ---- MLP layer 1 (scalar fp32, 1 edge/thread) ----
        const float* sW1 = sm + (path ? SM_W1V : SM_W1K);
        const float* sB1 = sm + (path ? SM_B1V : SM_B1K);
        float h[32];
        {
            u64 ef2[16];
            const float4* p4 = (const float4*)(ef_g + (size_t)e * 32);
#pragma unroll
            for (int i = 0; i < 8; i++) {
                float4 v = __ldg(p4 + i);
                ef2[2 * i] = pack2(v.x, v.y);
                ef2[2 * i + 1] = pack2(v.z, v.w);
            }
#pragma unroll 4
            for (int c = 0; c < 32; c++) {
                const ulonglong2* wp = (const ulonglong2*)(sW1 + c * 32);
                u64 a0 = 0, a1 = 0;
#pragma unroll
                for (int j = 0; j < 4; j++) {
                    ulonglong2 w1 = wp[2 * j], w2 = wp[2 * j + 1];
                    a0 = fma2(ef2[4 * j + 0], w1.x, a0);
                    a1 = fma2(ef2[4 * j + 1], w1.y, a1);
                    a0 = fma2(ef2[4 * j + 2], w2.x, a0);
                    a1 = fma2(ef2[4 * j + 3], w2.y, a1);
                }
                h[c] = fmaxf(sum2(a0) + sum2(a1) + sB1[c], 0.0f);
            }
        }

        // ---- store A row: [h_hi(32) | h_lo(32) | h_hi(32) | 1,1 | zeros] (pad-120) ----
        {
            u32* A32 = (u32*)sm + tid * 60;
#pragma unroll
            for (int j = 0; j < 16; j++)
                A32[j] = (u32)f2bf(h[2 * j]) | ((u32)f2bf(h[2 * j + 1]) << 16);
#pragma unroll
            for (int j = 0; j < 16; j++) {
                float x0 = h[2 * j], x1 = h[2 * j + 1];
                u16 l0 = f2bf(x0 - bf2f(f2bf(x0)));
                u16 l1 = f2bf(x1 - bf2f(f2bf(x1)));
                A32[16 + j] = (u32)l0 | ((u32)l1 << 16);
            }
#pragma unroll
            for (int j = 0; j < 16; j++)
                A32[32 + j] = (u32)f2bf(h[2 * j]) | ((u32)f2bf(h[2 * j + 1]) << 16);
            A32[48] = 0x3F803F80u;
#pragma unroll
            for (int j = 49; j < 60; j++) A32[j] = 0;
        }

        // ---- per-edge TP coefficients into slab ----
        int dst = __ldg(eidx + e);
        float4 sh4 = __ldg(((const float4*)sh_g) + e);
        {
            float* sl = sm + SM_SLAB + tid * 77;
            const float4* p4 = (const float4*)(atom + (size_t)dst * 40);
            float xv[24];
#pragma unroll
            for (int i = 0; i < 4; i++) {
                float4 v = __ldg(p4 + i);
                sl[4 * i] = v.x; sl[4 * i + 1] = v.y; sl[4 * i + 2] = v.z; sl[4 * i + 3] = v.w;
            }
#pragma unroll
            for (int i = 0; i < 6; i++) {
                float4 v = __ldg(p4 + 4 + i);
                xv[4 * i] = v.x; xv[4 * i + 1] = v.y; xv[4 * i + 2] = v.z; xv[4 * i + 3] = v.w;
            }
            sl[24] = sh4.x; sl[25] = sh4.y; sl[26] = sh4.z; sl[27] = sh4.w;
#pragma unroll
            for (int i = 0; i < 8; i++) {
                float a0 = xv[3 * i], a1 = xv[3 * i + 1], a2 = xv[3 * i + 2];
                sl[16 + i] = C110 * (a0 * sh4.y + a1 * sh4.z + a2 * sh4.w);
                sl[28 + 3 * i + 0] = a0; sl[28 + 3 * i + 1] = a1; sl[28 + 3 * i + 2] = a2;
                sl[52 + 3 * i + 0] = C111 * (a1 * sh4.w - a2 * sh4.z);
                sl[52 + 3 * i + 1] = C111 * (a2 * sh4.y - a0 * sh4.w);
                sl[52 + 3 * i + 2] = C111 * (a0 * sh4.z - a1 * sh4.y);
            }
        }
        __syncthreads();

        // ---- load A fragments (2 m-tiles x 7 k-steps) ----
        u32 af[2][7][4];
#pragma unroll
        for (int t = 0; t < 2; t++)
#pragma unroll
            for (int s = 0; s < 7; s++) {
                u32 addr = sA + ((u32)(warp * 32 + t * 16 + (lane & 15)) * 120 +
                                 (u32)(s * 16 + (lane >> 4) * 8)) * 2;
                LDMATRIX_X4(af[t][s][0], af[t][s][1], af[t][s][2], af[t][s][3], addr);
            }

        // per-row slab bases + constants (rows q, q+8, q+16, q+24 of this warp)
        const float* slr[4];
        float shs_r[4], s_r[4][3];
#pragma unroll
        for (int r = 0; r < 4; r++) {
            slr[r] = sm + SM_SLAB + (warp * 32 + q + 8 * r) * 77;
            shs_r[r] = slr[r][24];
            s_r[r][0] = slr[r][25]; s_r[r][1] = slr[r][26]; s_r[r][2] = slr[r][27];
        }

        float osA[4][4], ovA[4][6];
#pragma unroll
        for (int r = 0; r < 4; r++) {
#pragma unroll
            for (int s = 0; s < 4; s++) osA[r][s] = 0.0f;
#pragma unroll
            for (int s = 0; s < 6; s++) ovA[r][s] = 0.0f;
        }

        const u64* WF = g_Wfrag + (size_t)path * 80 * 7 * 32;

#define MMA_NG(NG, D) do {                                                       \
        u64 bf[7];                                                               \
        _Pragma("unroll")                                                        \
        for (int s = 0; s < 7; s++) bf[s] = __ldg(WF + ((NG) * 7 + s) * 32 + lane); \
        _Pragma("unroll")                                                        \
        for (int t = 0; t < 2; t++) {                                            \
            D[4 * t] = 0.0f; D[4 * t + 1] = 0.0f; D[4 * t + 2] = 0.0f; D[4 * t + 3] = 0.0f; \
            _Pragma("unroll")                                                    \
            for (int s = 0; s < 7; s++)                                          \
                MMA_BF16(D[4 * t], D[4 * t + 1], D[4 * t + 2], D[4 * t + 3],     \
                         af[t][s][0], af[t][s][1], af[t][s][2], af[t][s][3],     \
                         (u32)bf[s], (u32)(bf[s] >> 32));                        \
        } } while (0)

        // blocks 1+2 (ngroups 0..47): scalar outputs
#pragma unroll 1
        for (int g2 = 0; g2 < 24; g2++) {
#pragma unroll
            for (int par = 0; par < 2; par++) {
                int ng = 2 * g2 + par;
                float d[8];
                MMA_NG(ng, d);
                float ci[4];
                if (g2 < 16) {
#pragma unroll
                    for (int r = 0; r < 4; r++) ci[r] = slr[r][g2] * shs_r[r];
                } else {
#pragma unroll
                    for (int r = 0; r < 4; r++) ci[r] = slr[r][16 + (g2 - 16)];
                }
                const int slb = par * 2;
#pragma unroll
                for (int t = 0; t < 2; t++) {
                    osA[2 * t + 0][slb + 0] = fmaf(ci[2 * t + 0], d[4 * t + 0], osA[2 * t + 0][slb + 0]);
                    osA[2 * t + 0][slb + 1] = fmaf(ci[2 * t + 0], d[4 * t + 1], osA[2 * t + 0][slb + 1]);
                    osA[2 * t + 1][slb + 0] = fmaf(ci[2 * t + 1], d[4 * t + 2], osA[2 * t + 1][slb + 0]);
                    osA[2 * t + 1][slb + 1] = fmaf(ci[2 * t + 1], d[4 * t + 3], osA[2 * t + 1][slb + 1]);
                }
            }
        }
        // block 3 (ngroups 48..63): ov += (xs[i]*d) * sh_v
#pragma unroll 1
        for (int i = 0; i < 16; i++) {
            float d[8];
            MMA_NG(48 + i, d);
#pragma unroll
            for (int t = 0; t < 2; t++)
#pragma unroll
                for (int rr = 0; rr < 2; rr++) {
                    int r = 2 * t + rr;
                    float ci = slr[r][i];
#pragma unroll
                    for (int j = 0; j < 2; j++) {
                        float tv = ci * d[4 * t + 2 * rr + j];
                        ovA[r][3 * j + 0] = fmaf(tv, s_r[r][0], ovA[r][3 * j + 0]);
                        ovA[r][3 * j + 1] = fmaf(tv, s_r[r][1], ovA[r][3 * j + 1]);
                        ovA[r][3 * j + 2] = fmaf(tv, s_r[r][2], ovA[r][3 * j + 2]);
                    }
                }
        }
        // block 4 (ngroups 64..71): ov += (shs*d) * xv[i]
#pragma unroll 1
        for (int i = 0; i < 8; i++) {
            float d[8];
            MMA_NG(64 + i, d);
#pragma unroll
            for (int t = 0; t < 2; t++)
#pragma unroll
                for (int rr = 0; rr < 2; rr++) {
                    int r = 2 * t + rr;
                    float x0 = slr[r][28 + 3 * i], x1 = slr[r][29 + 3 * i], x2 = slr[r][30 + 3 * i];
#pragma unroll
                    for (int j = 0; j < 2; j++) {
                        float tv = shs_r[r] * d[4 * t + 2 * rr + j];
                        ovA[r][3 * j + 0] = fmaf(tv, x0, ovA[r][3 * j + 0]);
                        ovA[r][3 * j + 1] = fmaf(tv, x1, ovA[r][3 * j + 1]);
                        ovA[r][3 * j + 2] = fmaf(tv, x2, ovA[r][3 * j + 2]);
                    }
                }
        }
        // block 5 (ngroups 72..79): ov += d * crs[i]
#pragma unroll 1
        for (int i = 0; i < 8; i++) {
            float d[8];
            MMA_NG(72 + i, d);
#pragma unroll
            for (int t = 0; t < 2; t++)
#pragma unroll
                for (int rr = 0; rr < 2; rr++) {
                    int r = 2 * t + rr;
                    float c0 = slr[r][52 + 3 * i], c1 = slr[r][53 + 3 * i], c2 = slr[r][54 + 3 * i];
#pragma unroll
                    for (int j = 0; j < 2; j++) {
                        float dv = d[4 * t + 2 * rr + j];
                        ovA[r][3 * j + 0] = fmaf(dv, c0, ovA[r][3 * j + 0]);
                        ovA[r][3 * j + 1] = fmaf(dv, c1, ovA[r][3 * j + 1]);
                        ovA[r][3 * j + 2] = fmaf(dv, c2, ovA[r][3 * j + 2]);
                    }
                }
        }
#undef MMA_NG

        // ---- epilogue ----
        if (path == 0) {
#pragma unroll
            for (int r = 0; r < 4; r++) {
                int er = chunk * CHUNK + warp * 32 + q + 8 * r;
                int src = __ldg(eidx + N_EDGES + er);
                const float* qv = g_q + (size_t)src * 40;
                float a = 0.0f;
#pragma unroll
                for (int sl = 0; sl < 4; sl++) {
                    int o = (sl >> 1) * 8 + 2 * m + (sl & 1);
                    a = fmaf(osA[r][sl], __ldg(qv + o), a);
                }
#pragma unroll
                for (int j = 0; j < 2; j++) {
                    int o = 2 * m + j;
#pragma unroll
                    for (int d = 0; d < 3; d++)
                        a = fmaf(ovA[r][3 * j + d], __ldg(qv + 16 + 3 * o + d), a);
                }
                a += __shfl_xor_sync(0xFFFFFFFFu, a, 1);
                a += __shfl_xor_sync(0xFFFFFFFFu, a, 2);
                if (m == 0) {
                    g_attn[er] = a;
                    atomicMax(&g_m[src], fkey(a));
                }
            }
        } else {
#pragma unroll
            for (int r = 0; r < 4; r++) {
                int er = chunk * CHUNK + warp * 32 + q + 8 * r;
#pragma unroll
                for (int sl = 0; sl < 4; sl++) {
                    int o = (sl >> 1) * 8 + 2 * m + (sl & 1);
                    g_vT[(size_t)o * N_EDGES + er] = osA[r][sl];
                }
#pragma unroll
                for (int j = 0; j < 2; j++) {
                    int o = 2 * m + j;
#pragma unroll
                    for (int d = 0; d < 3; d++)
                        g_vT[(size_t)(16 + 3 * o + d) * N_EDGES + er] = ovA[r][3 * j + d];
                }
            }
        }
    }
}

// ---------------- softmax accumulation ----------------
__global__ void k_soft(const int* __restrict__ eidx) {
    int e = blockIdx.x * 256 + threadIdx.x;
    if (e >= N_EDGES) return;
    int src = eidx[N_EDGES + e];
    float m = fdec(g_m[src]);
    float ex = expf(g_attn[e] - m);
    atomicAdd(&g_denom[src], ex);
#pragma unroll
    for (int f = 0; f < 40; f++) {
        atomicAdd(&g_numer[f * N_NODES + src], ex * g_vT[(size_t)f * N_EDGES + e]);
    }
}

// ---------------- pre-activation + batchnorm stats ----------------
__global__ void k_stats(const float* __restrict__ atom) {
    int f = blockIdx.y;
    int n = blockIdx.x * 256 + threadIdx.x;
    float pre = 0.0f;
    if (n < N_NODES) {
        float den = g_denom[n];
        float upd = (den > 0.0f) ? g_numer[f * N_NODES + n] / den : 0.0f;
        pre = atom[(size_t)n * 40 + f] + upd;
        g_pre[f * N_NODES + n] = pre;
    }
    float s = pre, ss = pre * pre;
    unsigned lane = threadIdx.x & 31, wd = threadIdx.x >> 5;
#pragma unroll
    for (int o = 16; o > 0; o >>= 1) {
        s += __shfl_down_sync(0xFFFFFFFFu, s, o);
        ss += __shfl_down_sync(0xFFFFFFFFu, ss, o);
    }
    __shared__ float rs[8], rss[8];
    if (lane == 0) { rs[wd] = s; rss[wd] = ss; }
    __syncthreads();
    if (threadIdx.x == 0) {
        float S = 0.0f, SS = 0.0f;
#pragma unroll
        for (int w = 0; w < 8; w++) { S += rs[w]; SS += rss[w]; }
        atomicAdd(&g_stats[f], S);
        atomicAdd(&g_stats[40 + f], SS);
    }
}

// ---------------- batchnorm finalize ----------------
__global__ void k_final(const float* __restrict__ bnws, const float* __restrict__ bnbs,
                        const float* __restrict__ bnwv, float* __restrict__ out) {
    int t = blockIdx.x * 256 + threadIdx.x;
    if (t >= 40 * N_NODES) return;
    int n = t / 40, f = t % 40;
    float pre = g_pre[f * N_NODES + n];
    float r;
    if (f < 16) {
        float mu = g_stats[f] * (1.0f / N_NODES);
        float var = g_stats[40 + f] * (1.0f / N_NODES) - mu * mu;
        r = (pre - mu) * rsqrtf(var + 1e-5f) * bnws[f] + bnbs[f];
    } else {
        int i = (f - 16) / 3;
        float nrm = (g_stats[40 + 16 + i * 3 + 0] + g_stats[40 + 16 + i * 3 + 1] +
                     g_stats[40 + 16 + i * 3 + 2]) * (1.0f / (3.0f * N_NODES));
        r = pre * rsqrtf(nrm + 1e-5f) * bnwv[i];
    }
    out[t] = r;
}

// ---------------- passthrough copy of edge_features ----------------
__global__ void k_copyef(const float* __restrict__ ef, float* __restrict__ out) {
    int t = blockIdx.x * 256 + threadIdx.x;
    if (t >= (N_EDGES * 32) / 4) return;
    ((float4*)out)[t] = ((const float4*)ef)[t];
}

// ---------------- launch ----------------
extern "C" void kernel_launch(void* const* d_in, const int* in_sizes, int n_in,
                              void* d_out, int out_size) {
    const float* atom = (const float*)d_in[0];
    const float* ef   = (const float*)d_in[1];
    const float* sh   = (const float*)d_in[2];
    const float* Wq_s = (const float*)d_in[3];
    const float* Wq_v = (const float*)d_in[4];
    const float* kw1  = (const float*)d_in[5];
    const float* kb1  = (const float*)d_in[6];
    const float* kw2  = (const float*)d_in[7];
    const float* kb2  = (const float*)d_in[8];
    const float* vw1  = (const float*)d_in[9];
    const float* vb1  = (const float*)d_in[10];
    const float* vw2  = (const float*)d_in[11];
    const float* vb2  = (const float*)d_in[12];
    const float* bnws = (const float*)d_in[13];
    const float* bnbs = (const float*)d_in[14];
    const float* bnwv = (const float*)d_in[15];
    const int*   eidx = (const int*)d_in[16];
    float* out = (float*)d_out;

    cudaFuncSetAttribute(k_edges, cudaFuncAttributeMaxDynamicSharedMemorySize, SMEM_BYTES);

    k_init<<<(40 * N_NODES + 255) / 256, 256>>>();
    k_q<<<(40 * N_NODES + 255) / 256, 256>>>(atom, Wq_s, Wq_v);
    k_wstk<<<(2 * 80 * 7 * 32 + 255) / 256, 256>>>(kw2, kb2, vw2, vb2);
    k_edges<<<EGRID, 128, SMEM_BYTES>>>(atom, ef, sh, eidx, kw1, kb1, vw1, vb1);
    k_soft<<<(N_EDGES + 255) / 256, 256>>>(eidx);
    dim3 gs((N_NODES + 255) / 256, 40);
    k_stats<<<gs, 256>>>(atom);
    k_final<<<(40 * N_NODES + 255) / 256, 256>>>(bnws, bnbs, bnwv, out);
    k_copyef<<<((N_EDGES * 32) / 4 + 255) / 256, 256>>>(ef, out + 40 * N_NODES);
}